// round 7
// baseline (speedup 1.0000x reference)
#include <cuda_runtime.h>
#include <cuda_bf16.h>
#include <math.h>
#include <stdint.h>

#define BB 8
#define NN 512
#define TT 64
#define NIN 64
#define NE 128
#define NH 128
#define NZ 512
#define NODES (BB*NN)   // 4096

// ---------------- persistent device scratch ----------------
__device__ float g_dinv[BB*NN];
__device__ __nv_bfloat16 g_An_hi[BB*NN*NN], g_An_lo[BB*NN*NN];
__device__ __nv_bfloat16 g_h_hi[2][NODES*NH], g_h_lo[2][NODES*NH];
__device__ float g_es[NODES*NE];
__device__ float g_esW[NODES*NZ];
__device__ float g_b0[NZ];
__device__ __nv_bfloat16 g_Wz_hi[256*NZ], g_Wz_lo[256*NZ];   // [k][n]
__device__ float g_c[NODES*NH];

// ---------------- helpers ----------------
__device__ __forceinline__ uint32_t smem_u32(const void* p) {
    uint32_t a;
    asm("{ .reg .u64 t; cvta.to.shared.u64 t, %1; cvt.u32.u64 %0, t; }" : "=r"(a) : "l"(p));
    return a;
}
__device__ __forceinline__ void ldsm4(uint32_t* r, uint32_t addr) {
    asm volatile("ldmatrix.sync.aligned.m8n8.x4.shared.b16 {%0,%1,%2,%3}, [%4];"
        : "=r"(r[0]), "=r"(r[1]), "=r"(r[2]), "=r"(r[3]) : "r"(addr));
}
__device__ __forceinline__ void ldsm4t(uint32_t* r, uint32_t addr) {
    asm volatile("ldmatrix.sync.aligned.m8n8.x4.trans.shared.b16 {%0,%1,%2,%3}, [%4];"
        : "=r"(r[0]), "=r"(r[1]), "=r"(r[2]), "=r"(r[3]) : "r"(addr));
}
__device__ __forceinline__ void mma_bf16(float* d, const uint32_t* a, const uint32_t* b) {
    asm volatile("mma.sync.aligned.m16n8k16.row.col.f32.bf16.bf16.f32 "
        "{%0,%1,%2,%3}, {%4,%5,%6,%7}, {%8,%9}, {%0,%1,%2,%3};"
        : "+f"(d[0]), "+f"(d[1]), "+f"(d[2]), "+f"(d[3])
        : "r"(a[0]), "r"(a[1]), "r"(a[2]), "r"(a[3]), "r"(b[0]), "r"(b[1]));
}
__device__ __forceinline__ void cpa16(uint32_t dst, const void* src) {
    asm volatile("cp.async.cg.shared.global [%0], [%1], 16;" :: "r"(dst), "l"(src));
}
__device__ __forceinline__ void cp_commit() {
    asm volatile("cp.async.commit_group;" ::: "memory");
}
__device__ __forceinline__ void cp_wait1() {
    asm volatile("cp.async.wait_group 1;" ::: "memory");
}
__device__ __forceinline__ void cp_wait0() {
    asm volatile("cp.async.wait_group 0;" ::: "memory");
}
__device__ __forceinline__ void split_bf(float x, __nv_bfloat16& h, __nv_bfloat16& l) {
    h = __float2bfloat16(x);
    l = __float2bfloat16(x - __bfloat162float(h));
}
__device__ __forceinline__ float sigf(float x) { return 1.f / (1.f + __expf(-x)); }

// ---------------- setup kernels ----------------
__global__ void k_dinv(const float* __restrict__ A) {
    int row = blockIdx.x;
    const float* ap = A + (size_t)row * NN;
    float s = 0.f;
    for (int i = threadIdx.x; i < NN; i += 128) s += ap[i];
    __shared__ float red[4];
    for (int o = 16; o; o >>= 1) s += __shfl_xor_sync(0xffffffffu, s, o);
    if ((threadIdx.x & 31) == 0) red[threadIdx.x >> 5] = s;
    __syncthreads();
    if (threadIdx.x == 0) {
        float d = red[0] + red[1] + red[2] + red[3];
        g_dinv[row] = d > 0.f ? rsqrtf(d) : 0.f;
    }
}

__global__ void k_an(const float* __restrict__ A) {
    int idx = blockIdx.x * 256 + threadIdx.x;
    int b = idx / (NN * NN);
    int r = (idx / NN) % NN;
    int m = idx % NN;
    float v = A[idx] * g_dinv[b * NN + r] * g_dinv[b * NN + m];
    split_bf(v, g_An_hi[idx], g_An_lo[idx]);
}

__global__ void k_es(const float* __restrict__ X, const float* __restrict__ Wse,
                     const float* __restrict__ bse, float* __restrict__ out) {
    int idx = blockIdx.x * 256 + threadIdx.x;
    int node = idx >> 7, j = idx & 127;
    const float* x0 = X + (size_t)node * TT * NIN;
    float acc = bse[j];
    #pragma unroll
    for (int q = 0; q < NIN; q++) acc += x0[q] * Wse[q * NE + j];
    g_es[idx] = acc;
    if (j < NIN) out[(size_t)node * TT * NIN + j] = x0[j];
}

__global__ void k_wz(const float* __restrict__ Wpe, const float* __restrict__ bpe,
    const float* __restrict__ Wii, const float* __restrict__ bii,
    const float* __restrict__ Whi, const float* __restrict__ bhi,
    const float* __restrict__ Wif, const float* __restrict__ bif,
    const float* __restrict__ Whf, const float* __restrict__ bhf,
    const float* __restrict__ Wig, const float* __restrict__ big,
    const float* __restrict__ Whg, const float* __restrict__ bhg,
    const float* __restrict__ Wio, const float* __restrict__ bio,
    const float* __restrict__ Who, const float* __restrict__ bho) {
    int idx = blockIdx.x * 256 + threadIdx.x;   // [k][n]
    int k = idx >> 9, n = idx & 511;
    int ch = n >> 2, g = n & 3;
    const float* Wg  = g == 0 ? Wii : g == 1 ? Wif : g == 2 ? Wig : Wio;
    const float* Whx = g == 0 ? Whi : g == 1 ? Whf : g == 2 ? Whg : Who;
    float v;
    if (k < 128) {
        v = 0.f;
        for (int p = 0; p < NE; p++) v += Wpe[k * NE + p] * Wg[(NE + p) * NH + ch];
    } else {
        v = Whx[(k - 128) * NH + ch];
    }
    split_bf(v, g_Wz_hi[idx], g_Wz_lo[idx]);
    if (k == 0) {
        const float* bg  = g == 0 ? bii : g == 1 ? bif : g == 2 ? big : bio;
        const float* bhx = g == 0 ? bhi : g == 1 ? bhf : g == 2 ? bhg : bho;
        float bv = bg[ch] + bhx[ch];
        for (int p = 0; p < NE; p++) bv += bpe[p] * Wg[(NE + p) * NH + ch];
        g_b0[n] = bv;
    }
}

__global__ void k_esw(const float* __restrict__ Wii, const float* __restrict__ Wif,
                      const float* __restrict__ Wig, const float* __restrict__ Wio) {
    int idx = blockIdx.x * 256 + threadIdx.x;
    int node = idx >> 9, j = idx & 511;
    int ch = j >> 2, g = j & 3;
    const float* Wg = g == 0 ? Wii : g == 1 ? Wif : g == 2 ? Wig : Wio;
    const float* e = g_es + (size_t)node * NE;
    float acc = g_b0[j];
    for (int p = 0; p < NE; p++) acc += e[p] * Wg[p * NH + ch];
    g_esW[idx] = acc;
}

__global__ void k_zero() {
    int idx = blockIdx.x * 256 + threadIdx.x;
    g_c[idx] = 0.f;
    __nv_bfloat16 z = __float2bfloat16(0.f);
    g_h_hi[0][idx] = z;
    g_h_lo[0][idx] = z;
}

// ---------------- smem layout (bytes) ----------------
// HH [32][264] bf16 hi+lo (A operand for phase B: cols 0-127 H, 128-255 h)
#define S_HH_HI   0u
#define S_HH_LO   16896u
// pipeline region @33792: phase A buffers 2x44032, phase B W buffers 2x33792, phase C wo
#define S_PIPE    33792u
#define PA_BUF(s) (S_PIPE + (s) * 44032u)
#define PA_ANH    0u
#define PA_ANL    4608u
#define PA_HCH    9216u
#define PA_HCL    26624u
#define PB_BUF(s) (S_PIPE + (s) * 33792u)
#define PB_WL     16896u
#define S_ZB      121856u     // [32][260] f32
#define S_HN      155136u     // [32][132] f32
#define S_SC      172160u     // [32][132] f32 (c state)
#define SMEM_TOT  189056

// ---------------- fused per-step kernel ----------------
// grid 128 (node tiles of 32), block 256 (8 warps)
__global__ __launch_bounds__(256, 1) void k_step(int t, const float* __restrict__ Wout,
                                                 const float* __restrict__ bout,
                                                 float* __restrict__ out) {
    extern __shared__ char sm[];
    uint32_t smb = smem_u32(sm);
    int tid = threadIdx.x, lane = tid & 31, w = tid >> 5;
    long node0 = (long)blockIdx.x * 32;
    int b = (int)(node0 >> 9);
    int pp = (t + 1) & 1, pn = t & 1;
    const __nv_bfloat16* hp_hi = g_h_hi[pp];
    const __nv_bfloat16* hp_lo = g_h_lo[pp];

    // ldmatrix lane address components
    int a_r = (lane & 7) + ((lane >> 3) & 1) * 8;   // A x4
    int a_c = ((lane >> 4) & 1) * 8;
    int bt_r = lane & 15;                           // B x4.trans
    int bt_c = ((lane >> 4) & 1) * 8;

    int wm = w >> 2, wn = w & 3;

    // ---- phase A prefetch chunks 0,1 ----
    {
        #pragma unroll
        for (int s = 0; s < 2; s++) {
            uint32_t pb = smb + PA_BUF(s);
            int row = tid >> 3, seg = tid & 7;
            cpa16(pb + PA_ANH + (uint32_t)(row * 72 + seg * 8) * 2,
                  g_An_hi + (node0 + row) * (long)NN + s * 64 + seg * 8);
            cpa16(pb + PA_ANL + (uint32_t)(row * 72 + seg * 8) * 2,
                  g_An_lo + (node0 + row) * (long)NN + s * 64 + seg * 8);
            #pragma unroll
            for (int i = 0; i < 4; i++) {
                int idx = i * 256 + tid;
                int hr = idx >> 4, hs = idx & 15;
                long src = ((long)b * NN + s * 64 + hr) * NH + hs * 8;
                cpa16(pb + PA_HCH + (uint32_t)(hr * 136 + hs * 8) * 2, hp_hi + src);
                cpa16(pb + PA_HCL + (uint32_t)(hr * 136 + hs * 8) * 2, hp_lo + src);
            }
            cp_commit();
        }
    }

    // ---- own h rows -> HH cols 128-255; c state -> sc (plain loads) ----
    {
        #pragma unroll
        for (int i = 0; i < 2; i++) {
            int idx = i * 256 + tid;
            int row = idx >> 4, seg = idx & 15;
            const uint4* sH = (const uint4*)(hp_hi + (node0 + row) * NH) + seg;
            const uint4* sL = (const uint4*)(hp_lo + (node0 + row) * NH) + seg;
            *(uint4*)(sm + S_HH_HI + (row * 264 + 128 + seg * 8) * 2) = *sH;
            *(uint4*)(sm + S_HH_LO + (row * 264 + 128 + seg * 8) * 2) = *sL;
        }
        float* sc = (float*)(sm + S_SC);
        #pragma unroll
        for (int i = 0; i < 4; i++) {
            int idx = i * 256 + tid;
            int row = idx >> 5, c4 = (idx & 31) * 4;
            *(float4*)(sc + row * 132 + c4) = *(const float4*)(g_c + (node0 + row) * NH + c4);
        }
    }

    // ---- Phase A: H = An @ h (8 K-chunks of 64, 2-stage cp.async pipeline) ----
    float accA[4][4];
    #pragma unroll
    for (int nt = 0; nt < 4; nt++)
        #pragma unroll
        for (int q = 0; q < 4; q++) accA[nt][q] = 0.f;

    for (int c = 0; c < 8; c++) {
        if (c < 7) cp_wait1(); else cp_wait0();
        __syncthreads();
        uint32_t pb = smb + PA_BUF(c & 1);
        #pragma unroll
        for (int kk = 0; kk < 4; kk++) {
            uint32_t aH[4], aL[4];
            uint32_t aoff = (uint32_t)(((wm * 16 + a_r) * 72 + kk * 16 + a_c) * 2);
            ldsm4(aH, pb + PA_ANH + aoff);
            ldsm4(aL, pb + PA_ANL + aoff);
            #pragma unroll
            for (int p = 0; p < 2; p++) {
                uint32_t bH[4], bL[4];
                uint32_t boff = (uint32_t)(((kk * 16 + bt_r) * 136 + wn * 32 + p * 16 + bt_c) * 2);
                ldsm4t(bH, pb + PA_HCH + boff);
                ldsm4t(bL, pb + PA_HCL + boff);
                mma_bf16(accA[2 * p], aH, bH);
                mma_bf16(accA[2 * p], aH, bL);
                mma_bf16(accA[2 * p], aL, bH);
                mma_bf16(accA[2 * p + 1], aH, bH + 2);
                mma_bf16(accA[2 * p + 1], aH, bL + 2);
                mma_bf16(accA[2 * p + 1], aL, bH + 2);
            }
        }
        __syncthreads();
        if (c < 6) {
            int cn = c + 2;
            uint32_t pb2 = smb + PA_BUF(c & 1);
            int row = tid >> 3, seg = tid & 7;
            cpa16(pb2 + PA_ANH + (uint32_t)(row * 72 + seg * 8) * 2,
                  g_An_hi + (node0 + row) * (long)NN + cn * 64 + seg * 8);
            cpa16(pb2 + PA_ANL + (uint32_t)(row * 72 + seg * 8) * 2,
                  g_An_lo + (node0 + row) * (long)NN + cn * 64 + seg * 8);
            #pragma unroll
            for (int i = 0; i < 4; i++) {
                int idx = i * 256 + tid;
                int hr = idx >> 4, hs = idx & 15;
                long src = ((long)b * NN + cn * 64 + hr) * NH + hs * 8;
                cpa16(pb2 + PA_HCH + (uint32_t)(hr * 136 + hs * 8) * 2, hp_hi + src);
                cpa16(pb2 + PA_HCL + (uint32_t)(hr * 136 + hs * 8) * 2, hp_lo + src);
            }
            cp_commit();
        }
    }

    // ---- phase B prefetch W tiles 0,1 (overlaps HH epilogue) ----
    {
        #pragma unroll
        for (int s = 0; s < 2; s++) {           // tile w = s: nc=0, kc=s
            uint32_t wb = smb + PB_BUF(s);
            #pragma unroll
            for (int i = 0; i < 4; i++) {
                int idx = i * 256 + tid;
                int row = idx >> 5, seg = idx & 31;
                long src = (long)(s * 32 + row) * NZ + seg * 8;
                cpa16(wb + (uint32_t)(row * 264 + seg * 8) * 2, g_Wz_hi + src);
                cpa16(wb + PB_WL + (uint32_t)(row * 264 + seg * 8) * 2, g_Wz_lo + src);
            }
            cp_commit();
        }
    }

    // ---- HH epilogue: split H into cols 0-127 ----
    {
        int r0 = wm * 16 + (lane >> 2), r1 = r0 + 8;
        #pragma unroll
        for (int nt = 0; nt < 4; nt++) {
            int col = wn * 32 + (nt >> 1) * 16 + (nt & 1) * 8 + (lane & 3) * 2;
            __nv_bfloat16 h0, l0, h1, l1;
            split_bf(accA[nt][0], h0, l0); split_bf(accA[nt][1], h1, l1);
            __nv_bfloat162 ph; ph.x = h0; ph.y = h1;
            __nv_bfloat162 pl; pl.x = l0; pl.y = l1;
            *(__nv_bfloat162*)(sm + S_HH_HI + (r0 * 264 + col) * 2) = ph;
            *(__nv_bfloat162*)(sm + S_HH_LO + (r0 * 264 + col) * 2) = pl;
            split_bf(accA[nt][2], h0, l0); split_bf(accA[nt][3], h1, l1);
            ph.x = h0; ph.y = h1; pl.x = l0; pl.y = l1;
            *(__nv_bfloat162*)(sm + S_HH_HI + (r1 * 264 + col) * 2) = ph;
            *(__nv_bfloat162*)(sm + S_HH_LO + (r1 * 264 + col) * 2) = pl;
        }
    }

    // ---- Phase B: z = esW + [H|h] @ Wz (16 W tiles, pipelined; gates per nc) ----
    float* zb = (float*)(sm + S_ZB);
    float* hn = (float*)(sm + S_HN);
    float* sc = (float*)(sm + S_SC);
    float accB[8][4];
    #pragma unroll
    for (int nt = 0; nt < 8; nt++)
        #pragma unroll
        for (int q = 0; q < 4; q++) accB[nt][q] = 0.f;

    for (int wt = 0; wt < 16; wt++) {
        if (wt < 15) cp_wait1(); else cp_wait0();
        __syncthreads();
        int kc = wt & 7;
        uint32_t wb = smb + PB_BUF(wt & 1);
        #pragma unroll
        for (int kk = 0; kk < 2; kk++) {
            uint32_t aH[4], aL[4];
            uint32_t aoff = (uint32_t)(((wm * 16 + a_r) * 264 + kc * 32 + kk * 16 + a_c) * 2);
            ldsm4(aH, smb + S_HH_HI + aoff);
            ldsm4(aL, smb + S_HH_LO + aoff);
            #pragma unroll
            for (int p = 0; p < 4; p++) {
                uint32_t bH[4], bL[4];
                uint32_t boff = (uint32_t)(((kk * 16 + bt_r) * 264 + wn * 64 + p * 16 + bt_c) * 2);
                ldsm4t(bH, wb + boff);
                ldsm4t(bL, wb + PB_WL + boff);
                mma_bf16(accB[2 * p], aH, bH);
                mma_bf16(accB[2 * p], aH, bL);
                mma_bf16(accB[2 * p], aL, bH);
                mma_bf16(accB[2 * p + 1], aH, bH + 2);
                mma_bf16(accB[2 * p + 1], aH, bL + 2);
                mma_bf16(accB[2 * p + 1], aL, bH + 2);
            }
        }
        __syncthreads();
        if (wt < 14) {
            int w2 = wt + 2;
            int nc2 = w2 >> 3, kc2 = w2 & 7;
            uint32_t wb2 = smb + PB_BUF(wt & 1);
            #pragma unroll
            for (int i = 0; i < 4; i++) {
                int idx = i * 256 + tid;
                int row = idx >> 5, seg = idx & 31;
                long src = (long)(kc2 * 32 + row) * NZ + nc2 * 256 + seg * 8;
                cpa16(wb2 + (uint32_t)(row * 264 + seg * 8) * 2, g_Wz_hi + src);
                cpa16(wb2 + PB_WL + (uint32_t)(row * 264 + seg * 8) * 2, g_Wz_lo + src);
            }
            cp_commit();
        }
        if ((wt & 7) == 7) {
            int nc = wt >> 3;
            // write accums to zb
            {
                int r0 = wm * 16 + (lane >> 2), r1 = r0 + 8;
                #pragma unroll
                for (int nt = 0; nt < 8; nt++) {
                    int col = wn * 64 + (nt >> 1) * 16 + (nt & 1) * 8 + (lane & 3) * 2;
                    zb[r0 * 260 + col]     = accB[nt][0];
                    zb[r0 * 260 + col + 1] = accB[nt][1];
                    zb[r1 * 260 + col]     = accB[nt][2];
                    zb[r1 * 260 + col + 1] = accB[nt][3];
                    #pragma unroll
                    for (int q = 0; q < 4; q++) accB[nt][q] = 0.f;
                }
            }
            __syncthreads();
            // gates: thread = (row = tid>>3, g8 = tid&7), channels nc*64 + q*8 + g8
            {
                int row = tid >> 3, g8 = tid & 7;
                long node = node0 + row;
                #pragma unroll
                for (int q = 0; q < 8; q++) {
                    int ch = nc * 64 + q * 8 + g8;
                    int colz = q * 32 + g8 * 4;
                    float4 z4 = *(const float4*)(zb + row * 260 + colz);
                    float4 e4 = *(const float4*)(g_esW + node * NZ + nc * 256 + colz);
                    float it = sigf(z4.x + e4.x);
                    float ft = sigf(z4.y + e4.y);
                    float gt = tanhf(z4.z + e4.z);
                    float ot = sigf(z4.w + e4.w);
                    float cn = ft * sc[row * 132 + ch] + it * gt;
                    float hv = ot * tanhf(cn);
                    sc[row * 132 + ch] = cn;
                    hn[row * 132 + ch] = hv;
                }
            }
            __syncthreads();
        }
    }

    // ---- coalesced c / h writeback ----
    {
        __nv_bfloat16* hw_hi = g_h_hi[pn];
        __nv_bfloat16* hw_lo = g_h_lo[pn];
        #pragma unroll
        for (int i = 0; i < 4; i++) {
            int idx = i * 256 + tid;
            int row = idx >> 5, c4 = (idx & 31) * 4;
            long base = (node0 + row) * NH + c4;
            *(float4*)(g_c + base) = *(const float4*)(sc + row * 132 + c4);
            float4 hv4 = *(const float4*)(hn + row * 132 + c4);
            __nv_bfloat16 hh[4], hl[4];
            split_bf(hv4.x, hh[0], hl[0]); split_bf(hv4.y, hh[1], hl[1]);
            split_bf(hv4.z, hh[2], hl[2]); split_bf(hv4.w, hh[3], hl[3]);
            *(uint2*)(hw_hi + base) = *(const uint2*)hh;
            *(uint2*)(hw_lo + base) = *(const uint2*)hl;
        }
    }

    // ---- Phase C: out[t] = out[t-1] + h_new @ Wout + bout (exact fp32) ----
    float* wo = (float*)(sm + S_PIPE);
    #pragma unroll
    for (int i = 0; i < 8; i++) {
        int idx = i * 256 + tid;
        int row = idx >> 4, c4 = (idx & 15) * 4;
        *(float4*)(wo + row * 68 + c4) = *(const float4*)(Wout + row * NIN + c4);
    }
    __syncthreads();
    {
        int row = tid >> 3, c8 = (tid & 7) * 8;
        long node = node0 + row;
        float o[8];
        *(float4*)(o)     = *(const float4*)(bout + c8);
        *(float4*)(o + 4) = *(const float4*)(bout + c8 + 4);
        #pragma unroll 4
        for (int k = 0; k < NH; k++) {
            float hv = hn[row * 132 + k];
            float4 w0 = *(const float4*)(wo + k * 68 + c8);
            float4 w1 = *(const float4*)(wo + k * 68 + c8 + 4);
            o[0] += hv * w0.x; o[1] += hv * w0.y;
            o[2] += hv * w0.z; o[3] += hv * w0.w;
            o[4] += hv * w1.x; o[5] += hv * w1.y;
            o[6] += hv * w1.z; o[7] += hv * w1.w;
        }
        long pb = (node * TT + (t - 1)) * NIN + c8;
        long ob = (node * TT + t) * NIN + c8;
        float4 p0 = *(const float4*)(out + pb);
        float4 p1 = *(const float4*)(out + pb + 4);
        float4 w0 = make_float4(p0.x + o[0], p0.y + o[1], p0.z + o[2], p0.w + o[3]);
        float4 w1 = make_float4(p1.x + o[4], p1.y + o[5], p1.z + o[6], p1.w + o[7]);
        *(float4*)(out + ob)     = w0;
        *(float4*)(out + ob + 4) = w1;
    }
}

// ---------------- launch ----------------
extern "C" void kernel_launch(void* const* d_in, const int* in_sizes, int n_in,
                              void* d_out, int out_size) {
    (void)in_sizes; (void)n_in; (void)out_size;
    const float* X    = (const float*)d_in[0];
    const float* A    = (const float*)d_in[1];
    const float* Wse  = (const float*)d_in[2];
    const float* bse  = (const float*)d_in[3];
    const float* Wpe  = (const float*)d_in[4];
    const float* bpe  = (const float*)d_in[5];
    const float* Wii  = (const float*)d_in[6];
    const float* bii  = (const float*)d_in[7];
    const float* Whi  = (const float*)d_in[8];
    const float* bhi  = (const float*)d_in[9];
    const float* Wif  = (const float*)d_in[10];
    const float* bif  = (const float*)d_in[11];
    const float* Whf  = (const float*)d_in[12];
    const float* bhf  = (const float*)d_in[13];
    const float* Wig  = (const float*)d_in[14];
    const float* big  = (const float*)d_in[15];
    const float* Whg  = (const float*)d_in[16];
    const float* bhg  = (const float*)d_in[17];
    const float* Wio  = (const float*)d_in[18];
    const float* bio  = (const float*)d_in[19];
    const float* Who  = (const float*)d_in[20];
    const float* bho  = (const float*)d_in[21];
    const float* Wout = (const float*)d_in[22];
    const float* bout = (const float*)d_in[23];
    float* out = (float*)d_out;

    cudaFuncSetAttribute(k_step, cudaFuncAttributeMaxDynamicSharedMemorySize, SMEM_TOT);

    k_dinv<<<BB * NN, 128>>>(A);
    k_an<<<(BB * NN * NN) / 256, 256>>>(A);
    k_es<<<(NODES * NE) / 256, 256>>>(X, Wse, bse, out);
    k_wz<<<(256 * NZ) / 256, 256>>>(Wpe, bpe, Wii, bii, Whi, bhi, Wif, bif,
                                    Whf, bhf, Wig, big, Whg, bhg,
                                    Wio, bio, Who, bho);
    k_esw<<<(NODES * NZ) / 256, 256>>>(Wii, Wif, Wig, Wio);
    k_zero<<<(NODES * NH) / 256, 256>>>();

    for (int t = 1; t < TT; t++) {
        k_step<<<128, 256, SMEM_TOT>>>(t, Wout, bout, out);
    }
}

// round 8
// speedup vs baseline: 1.2361x; 1.2361x over previous
#include <cuda_runtime.h>
#include <cuda_fp16.h>
#include <math.h>
#include <stdint.h>

#define BB 8
#define NN 512
#define TT 64
#define NIN 64
#define NE 128
#define NH 128
#define NZ 512
#define NODES (BB*NN)   // 4096

// ---------------- persistent device scratch ----------------
__device__ float g_dinv[BB*NN];
__device__ __half g_An_hi[BB*NN*NN], g_An_lo[BB*NN*NN];
__device__ __half g_h_hi[2][NODES*NH], g_h_lo[2][NODES*NH];
__device__ float g_es[NODES*NE];
__device__ float g_esW[NODES*NZ];
__device__ float g_b0[NZ];
__device__ __half g_Wz[256*NZ];          // [k][n], fp16 (B operand, single)
__device__ float g_c[NODES*NH];

// ---------------- helpers ----------------
__device__ __forceinline__ uint32_t smem_u32(const void* p) {
    uint32_t a;
    asm("{ .reg .u64 t; cvta.to.shared.u64 t, %1; cvt.u32.u64 %0, t; }" : "=r"(a) : "l"(p));
    return a;
}
__device__ __forceinline__ void ldsm4(uint32_t* r, uint32_t addr) {
    asm volatile("ldmatrix.sync.aligned.m8n8.x4.shared.b16 {%0,%1,%2,%3}, [%4];"
        : "=r"(r[0]), "=r"(r[1]), "=r"(r[2]), "=r"(r[3]) : "r"(addr));
}
__device__ __forceinline__ void ldsm4t(uint32_t* r, uint32_t addr) {
    asm volatile("ldmatrix.sync.aligned.m8n8.x4.trans.shared.b16 {%0,%1,%2,%3}, [%4];"
        : "=r"(r[0]), "=r"(r[1]), "=r"(r[2]), "=r"(r[3]) : "r"(addr));
}
__device__ __forceinline__ void mma_f16(float* d, const uint32_t* a, const uint32_t* b) {
    asm volatile("mma.sync.aligned.m16n8k16.row.col.f32.f16.f16.f32 "
        "{%0,%1,%2,%3}, {%4,%5,%6,%7}, {%8,%9}, {%0,%1,%2,%3};"
        : "+f"(d[0]), "+f"(d[1]), "+f"(d[2]), "+f"(d[3])
        : "r"(a[0]), "r"(a[1]), "r"(a[2]), "r"(a[3]), "r"(b[0]), "r"(b[1]));
}
__device__ __forceinline__ void split_h(float x, __half& h, __half& l) {
    h = __float2half_rn(x);
    l = __float2half_rn(x - __half2float(h));
}
__device__ __forceinline__ float sigf(float x) { return 1.f / (1.f + __expf(-x)); }

// ---------------- setup kernels ----------------
__global__ void k_dinv(const float* __restrict__ A) {
    int row = blockIdx.x;
    const float* ap = A + (size_t)row * NN;
    float s = 0.f;
    for (int i = threadIdx.x; i < NN; i += 128) s += ap[i];
    __shared__ float red[4];
    for (int o = 16; o; o >>= 1) s += __shfl_xor_sync(0xffffffffu, s, o);
    if ((threadIdx.x & 31) == 0) red[threadIdx.x >> 5] = s;
    __syncthreads();
    if (threadIdx.x == 0) {
        float d = red[0] + red[1] + red[2] + red[3];
        g_dinv[row] = d > 0.f ? rsqrtf(d) : 0.f;
    }
}

__global__ void k_an(const float* __restrict__ A) {
    int idx = blockIdx.x * 256 + threadIdx.x;
    int b = idx / (NN * NN);
    int r = (idx / NN) % NN;
    int m = idx % NN;
    float v = A[idx] * g_dinv[b * NN + r] * g_dinv[b * NN + m];
    split_h(v, g_An_hi[idx], g_An_lo[idx]);
}

__global__ void k_es(const float* __restrict__ X, const float* __restrict__ Wse,
                     const float* __restrict__ bse, float* __restrict__ out) {
    int idx = blockIdx.x * 256 + threadIdx.x;
    int node = idx >> 7, j = idx & 127;
    const float* x0 = X + (size_t)node * TT * NIN;
    float acc = bse[j];
    #pragma unroll
    for (int q = 0; q < NIN; q++) acc += x0[q] * Wse[q * NE + j];
    g_es[idx] = acc;
    if (j < NIN) out[(size_t)node * TT * NIN + j] = x0[j];
}

__global__ void k_wz(const float* __restrict__ Wpe, const float* __restrict__ bpe,
    const float* __restrict__ Wii, const float* __restrict__ bii,
    const float* __restrict__ Whi, const float* __restrict__ bhi,
    const float* __restrict__ Wif, const float* __restrict__ bif,
    const float* __restrict__ Whf, const float* __restrict__ bhf,
    const float* __restrict__ Wig, const float* __restrict__ big,
    const float* __restrict__ Whg, const float* __restrict__ bhg,
    const float* __restrict__ Wio, const float* __restrict__ bio,
    const float* __restrict__ Who, const float* __restrict__ bho) {
    int idx = blockIdx.x * 256 + threadIdx.x;   // [k][n]
    int k = idx >> 9, n = idx & 511;
    int ch = n >> 2, g = n & 3;
    const float* Wg  = g == 0 ? Wii : g == 1 ? Wif : g == 2 ? Wig : Wio;
    const float* Whx = g == 0 ? Whi : g == 1 ? Whf : g == 2 ? Whg : Who;
    float v;
    if (k < 128) {
        v = 0.f;
        for (int p = 0; p < NE; p++) v += Wpe[k * NE + p] * Wg[(NE + p) * NH + ch];
    } else {
        v = Whx[(k - 128) * NH + ch];
    }
    g_Wz[idx] = __float2half_rn(v);
    if (k == 0) {
        const float* bg  = g == 0 ? bii : g == 1 ? bif : g == 2 ? big : bio;
        const float* bhx = g == 0 ? bhi : g == 1 ? bhf : g == 2 ? bhg : bho;
        float bv = bg[ch] + bhx[ch];
        for (int p = 0; p < NE; p++) bv += bpe[p] * Wg[(NE + p) * NH + ch];
        g_b0[n] = bv;
    }
}

__global__ void k_esw(const float* __restrict__ Wii, const float* __restrict__ Wif,
                      const float* __restrict__ Wig, const float* __restrict__ Wio) {
    int idx = blockIdx.x * 256 + threadIdx.x;
    int node = idx >> 9, j = idx & 511;
    int ch = j >> 2, g = j & 3;
    const float* Wg = g == 0 ? Wii : g == 1 ? Wif : g == 2 ? Wig : Wio;
    const float* e = g_es + (size_t)node * NE;
    float acc = g_b0[j];
    for (int p = 0; p < NE; p++) acc += e[p] * Wg[p * NH + ch];
    g_esW[idx] = acc;
}

__global__ void k_zero() {
    int idx = blockIdx.x * 256 + threadIdx.x;
    g_c[idx] = 0.f;
    __half z = __float2half(0.f);
    g_h_hi[0][idx] = z;
    g_h_lo[0][idx] = z;
}

// ---------------- smem layout (bytes) ----------------
// HH [32][264] fp16 hi+lo (phase-B A operand: cols 0-127 H, 128-255 h)
#define S_HH_HI   0u
#define S_HH_LO   16896u
// shared region @33792 (52224 bytes):
//   phase A: An hi [32][136] @0, An lo @8704, h hi [128][136] @17408
//   phase B: W [64][264] fp16 @0 (33792)
//   phase C: Wout f32 [128][68] @0 (34816)
#define S_PIPE    33792u
#define PA_ANH    0u
#define PA_ANL    8704u
#define PA_HCH    17408u
#define S_ZB      86016u      // [32][260] f32
#define S_HN      119296u     // [32][132] f32
#define S_SC      136192u     // [32][132] f32
#define SMEM_TOT  153088

// ---------------- fused per-step kernel ----------------
// grid 128 (node tiles of 32), block 256 (8 warps)
__global__ __launch_bounds__(256, 1) void k_step(int t, const float* __restrict__ Wout,
                                                 const float* __restrict__ bout,
                                                 float* __restrict__ out) {
    extern __shared__ char sm[];
    uint32_t smb = smem_u32(sm);
    int tid = threadIdx.x, lane = tid & 31, w = tid >> 5;
    long node0 = (long)blockIdx.x * 32;
    int b = (int)(node0 >> 9);
    int pp = (t + 1) & 1, pn = t & 1;
    const __half* hp_hi = g_h_hi[pp];
    const __half* hp_lo = g_h_lo[pp];

    // ldmatrix lane address components
    int a_r = (lane & 7) + ((lane >> 3) & 1) * 8;   // A x4
    int a_c = ((lane >> 4) & 1) * 8;
    int bt_r = lane & 15;                           // B x4.trans
    int bt_c = ((lane >> 4) & 1) * 8;
    int wm = w >> 2, wn = w & 3;

    // ---- own h rows -> HH cols 128-255 (hi/lo); c state -> sc ----
    {
        #pragma unroll
        for (int i = 0; i < 2; i++) {
            int idx = i * 256 + tid;
            int row = idx >> 4, seg = idx & 15;
            const uint4* sH = (const uint4*)(hp_hi + (node0 + row) * NH) + seg;
            const uint4* sL = (const uint4*)(hp_lo + (node0 + row) * NH) + seg;
            *(uint4*)(sm + S_HH_HI + (row * 264 + 128 + seg * 8) * 2) = *sH;
            *(uint4*)(sm + S_HH_LO + (row * 264 + 128 + seg * 8) * 2) = *sL;
        }
        float* sc = (float*)(sm + S_SC);
        #pragma unroll
        for (int i = 0; i < 4; i++) {
            int idx = i * 256 + tid;
            int row = idx >> 5, c4 = (idx & 31) * 4;
            *(float4*)(sc + row * 132 + c4) = *(const float4*)(g_c + (node0 + row) * NH + c4);
        }
    }

    // ---- Phase A: H = An @ h (4 K-chunks of 128; A split fp16, B single fp16) ----
    float accA[4][4];
    #pragma unroll
    for (int nt = 0; nt < 4; nt++)
        #pragma unroll
        for (int q = 0; q < 4; q++) accA[nt][q] = 0.f;

    for (int c = 0; c < 4; c++) {
        __syncthreads();
        // An chunk [32][128] hi/lo
        #pragma unroll
        for (int i = 0; i < 2; i++) {
            int idx = i * 256 + tid;
            int row = idx >> 4, seg = idx & 15;
            const uint4* sH = (const uint4*)(g_An_hi + (node0 + row) * (long)NN + c * 128) + seg;
            const uint4* sL = (const uint4*)(g_An_lo + (node0 + row) * (long)NN + c * 128) + seg;
            *(uint4*)(sm + S_PIPE + PA_ANH + (row * 136 + seg * 8) * 2) = *sH;
            *(uint4*)(sm + S_PIPE + PA_ANL + (row * 136 + seg * 8) * 2) = *sL;
        }
        // h chunk [128][128] hi only
        #pragma unroll
        for (int i = 0; i < 8; i++) {
            int idx = i * 256 + tid;
            int row = idx >> 4, seg = idx & 15;
            long nsrc = (long)b * NN + c * 128 + row;
            const uint4* sH = (const uint4*)(hp_hi + nsrc * NH) + seg;
            *(uint4*)(sm + S_PIPE + PA_HCH + (row * 136 + seg * 8) * 2) = *sH;
        }
        __syncthreads();
        #pragma unroll
        for (int kk = 0; kk < 8; kk++) {
            uint32_t aH[4], aL[4];
            uint32_t aoff = (uint32_t)(((wm * 16 + a_r) * 136 + kk * 16 + a_c) * 2);
            ldsm4(aH, smb + S_PIPE + PA_ANH + aoff);
            ldsm4(aL, smb + S_PIPE + PA_ANL + aoff);
            #pragma unroll
            for (int p = 0; p < 2; p++) {
                uint32_t bH[4];
                uint32_t boff = (uint32_t)(((kk * 16 + bt_r) * 136 + wn * 32 + p * 16 + bt_c) * 2);
                ldsm4t(bH, smb + S_PIPE + PA_HCH + boff);
                mma_f16(accA[2 * p],     aH, bH);
                mma_f16(accA[2 * p],     aL, bH);
                mma_f16(accA[2 * p + 1], aH, bH + 2);
                mma_f16(accA[2 * p + 1], aL, bH + 2);
            }
        }
    }
    __syncthreads();

    // ---- HH epilogue: split H into cols 0-127 ----
    {
        int r0 = wm * 16 + (lane >> 2), r1 = r0 + 8;
        #pragma unroll
        for (int nt = 0; nt < 4; nt++) {
            int col = wn * 32 + (nt >> 1) * 16 + (nt & 1) * 8 + (lane & 3) * 2;
            __half h0, l0, h1, l1;
            split_h(accA[nt][0], h0, l0); split_h(accA[nt][1], h1, l1);
            __half2 ph; ph.x = h0; ph.y = h1;
            __half2 pl; pl.x = l0; pl.y = l1;
            *(__half2*)(sm + S_HH_HI + (r0 * 264 + col) * 2) = ph;
            *(__half2*)(sm + S_HH_LO + (r0 * 264 + col) * 2) = pl;
            split_h(accA[nt][2], h0, l0); split_h(accA[nt][3], h1, l1);
            ph.x = h0; ph.y = h1; pl.x = l0; pl.y = l1;
            *(__half2*)(sm + S_HH_HI + (r1 * 264 + col) * 2) = ph;
            *(__half2*)(sm + S_HH_LO + (r1 * 264 + col) * 2) = pl;
        }
    }

    // ---- Phase B: z = esW + [H|h] @ Wz (A split, W single; gates per nc) ----
    float* zb = (float*)(sm + S_ZB);
    float* hn = (float*)(sm + S_HN);
    float* sc = (float*)(sm + S_SC);
    float accB[8][4];
    #pragma unroll
    for (int nt = 0; nt < 8; nt++)
        #pragma unroll
        for (int q = 0; q < 4; q++) accB[nt][q] = 0.f;

    for (int nc = 0; nc < 2; nc++) {
        for (int kc = 0; kc < 4; kc++) {
            __syncthreads();
            // W tile [64][256] fp16
            #pragma unroll
            for (int i = 0; i < 8; i++) {
                int idx = i * 256 + tid;
                int row = idx >> 5, seg = idx & 31;
                long src = (long)(kc * 64 + row) * NZ + nc * 256 + seg * 8;
                *(uint4*)(sm + S_PIPE + (row * 264 + seg * 8) * 2) =
                    *(const uint4*)(g_Wz + src);
            }
            __syncthreads();
            #pragma unroll
            for (int kk = 0; kk < 4; kk++) {
                uint32_t aH[4], aL[4];
                uint32_t aoff = (uint32_t)(((wm * 16 + a_r) * 264 + kc * 64 + kk * 16 + a_c) * 2);
                ldsm4(aH, smb + S_HH_HI + aoff);
                ldsm4(aL, smb + S_HH_LO + aoff);
                #pragma unroll
                for (int p = 0; p < 4; p++) {
                    uint32_t bH[4];
                    uint32_t boff = (uint32_t)(((kk * 16 + bt_r) * 264 + wn * 64 + p * 16 + bt_c) * 2);
                    ldsm4t(bH, smb + S_PIPE + boff);
                    mma_f16(accB[2 * p],     aH, bH);
                    mma_f16(accB[2 * p],     aL, bH);
                    mma_f16(accB[2 * p + 1], aH, bH + 2);
                    mma_f16(accB[2 * p + 1], aL, bH + 2);
                }
            }
        }
        __syncthreads();
        // accums -> zb
        {
            int r0 = wm * 16 + (lane >> 2), r1 = r0 + 8;
            #pragma unroll
            for (int nt = 0; nt < 8; nt++) {
                int col = wn * 64 + (nt >> 1) * 16 + (nt & 1) * 8 + (lane & 3) * 2;
                zb[r0 * 260 + col]     = accB[nt][0];
                zb[r0 * 260 + col + 1] = accB[nt][1];
                zb[r1 * 260 + col]     = accB[nt][2];
                zb[r1 * 260 + col + 1] = accB[nt][3];
                #pragma unroll
                for (int q = 0; q < 4; q++) accB[nt][q] = 0.f;
            }
        }
        __syncthreads();
        // gates: thread = (row = tid>>3, g8 = tid&7)
        {
            int row = tid >> 3, g8 = tid & 7;
            long node = node0 + row;
            #pragma unroll
            for (int q = 0; q < 8; q++) {
                int ch = nc * 64 + q * 8 + g8;
                int colz = q * 32 + g8 * 4;
                float4 z4 = *(const float4*)(zb + row * 260 + colz);
                float4 e4 = *(const float4*)(g_esW + node * NZ + nc * 256 + colz);
                float it = sigf(z4.x + e4.x);
                float ft = sigf(z4.y + e4.y);
                float gt = tanhf(z4.z + e4.z);
                float ot = sigf(z4.w + e4.w);
                float cn = ft * sc[row * 132 + ch] + it * gt;
                float hv = ot * tanhf(cn);
                sc[row * 132 + ch] = cn;
                hn[row * 132 + ch] = hv;
            }
        }
        __syncthreads();
    }

    // ---- coalesced c / h writeback ----
    {
        __half* hw_hi = g_h_hi[pn];
        __half* hw_lo = g_h_lo[pn];
        #pragma unroll
        for (int i = 0; i < 4; i++) {
            int idx = i * 256 + tid;
            int row = idx >> 5, c4 = (idx & 31) * 4;
            long base = (node0 + row) * NH + c4;
            *(float4*)(g_c + base) = *(const float4*)(sc + row * 132 + c4);
            float4 hv4 = *(const float4*)(hn + row * 132 + c4);
            __half hh[4], hl[4];
            split_h(hv4.x, hh[0], hl[0]); split_h(hv4.y, hh[1], hl[1]);
            split_h(hv4.z, hh[2], hl[2]); split_h(hv4.w, hh[3], hl[3]);
            *(uint2*)(hw_hi + base) = *(const uint2*)hh;
            *(uint2*)(hw_lo + base) = *(const uint2*)hl;
        }
    }

    // ---- Phase C: out[t] = out[t-1] + h_new @ Wout + bout (exact fp32) ----
    float* wo = (float*)(sm + S_PIPE);
    #pragma unroll
    for (int i = 0; i < 8; i++) {
        int idx = i * 256 + tid;
        int row = idx >> 4, c4 = (idx & 15) * 4;
        *(float4*)(wo + row * 68 + c4) = *(const float4*)(Wout + row * NIN + c4);
    }
    __syncthreads();
    {
        int row = tid >> 3, c8 = (tid & 7) * 8;
        long node = node0 + row;
        float o[8];
        *(float4*)(o)     = *(const float4*)(bout + c8);
        *(float4*)(o + 4) = *(const float4*)(bout + c8 + 4);
        #pragma unroll 4
        for (int k = 0; k < NH; k++) {
            float hv = hn[row * 132 + k];
            float4 w0 = *(const float4*)(wo + k * 68 + c8);
            float4 w1 = *(const float4*)(wo + k * 68 + c8 + 4);
            o[0] += hv * w0.x; o[1] += hv * w0.y;
            o[2] += hv * w0.z; o[3] += hv * w0.w;
            o[4] += hv * w1.x; o[5] += hv * w1.y;
            o[6] += hv * w1.z; o[7] += hv * w1.w;
        }
        long pb = (node * TT + (t - 1)) * NIN + c8;
        long ob = (node * TT + t) * NIN + c8;
        float4 p0 = *(const float4*)(out + pb);
        float4 p1 = *(const float4*)(out + pb + 4);
        float4 w0 = make_float4(p0.x + o[0], p0.y + o[1], p0.z + o[2], p0.w + o[3]);
        float4 w1 = make_float4(p1.x + o[4], p1.y + o[5], p1.z + o[6], p1.w + o[7]);
        *(float4*)(out + ob)     = w0;
        *(float4*)(out + ob + 4) = w1;
    }
}

// ---------------- launch ----------------
extern "C" void kernel_launch(void* const* d_in, const int* in_sizes, int n_in,
                              void* d_out, int out_size) {
    (void)in_sizes; (void)n_in; (void)out_size;
    const float* X    = (const float*)d_in[0];
    const float* A    = (const float*)d_in[1];
    const float* Wse  = (const float*)d_in[2];
    const float* bse  = (const float*)d_in[3];
    const float* Wpe  = (const float*)d_in[4];
    const float* bpe  = (const float*)d_in[5];
    const float* Wii  = (const float*)d_in[6];
    const float* bii  = (const float*)d_in[7];
    const float* Whi  = (const float*)d_in[8];
    const float* bhi  = (const float*)d_in[9];
    const float* Wif  = (const float*)d_in[10];
    const float* bif  = (const float*)d_in[11];
    const float* Whf  = (const float*)d_in[12];
    const float* bhf  = (const float*)d_in[13];
    const float* Wig  = (const float*)d_in[14];
    const float* big  = (const float*)d_in[15];
    const float* Whg  = (const float*)d_in[16];
    const float* bhg  = (const float*)d_in[17];
    const float* Wio  = (const float*)d_in[18];
    const float* bio  = (const float*)d_in[19];
    const float* Who  = (const float*)d_in[20];
    const float* bho  = (const float*)d_in[21];
    const float* Wout = (const float*)d_in[22];
    const float* bout = (const float*)d_in[23];
    float* out = (float*)d_out;

    cudaFuncSetAttribute(k_step, cudaFuncAttributeMaxDynamicSharedMemorySize, SMEM_TOT);

    k_dinv<<<BB * NN, 128>>>(A);
    k_an<<<(BB * NN * NN) / 256, 256>>>(A);
    k_es<<<(NODES * NE) / 256, 256>>>(X, Wse, bse, out);
    k_wz<<<(256 * NZ) / 256, 256>>>(Wpe, bpe, Wii, bii, Whi, bhi, Wif, bif,
                                    Whf, bhf, Wig, big, Whg, bhg,
                                    Wio, bio, Who, bho);
    k_esw<<<(NODES * NZ) / 256, 256>>>(Wii, Wif, Wig, Wio);
    k_zero<<<(NODES * NH) / 256, 256>>>();

    for (int t = 1; t < TT; t++) {
        k_step<<<128, 256, SMEM_TOT>>>(t, Wout, bout, out);
    }
}

// round 9
// speedup vs baseline: 1.2429x; 1.0055x over previous
#include <cuda_runtime.h>
#include <cuda_fp16.h>
#include <math.h>
#include <stdint.h>

#define BB 8
#define NN 512
#define TT 64
#define NIN 64
#define NE 128
#define NH 128
#define NZ 512
#define NODES (BB*NN)   // 4096

// ---------------- persistent device scratch ----------------
__device__ float g_dinv[BB*NN];
__device__ __half g_An_hi[BB*NN*NN], g_An_lo[BB*NN*NN];
__device__ __half g_h_hi[2][NODES*NH], g_h_lo[2][NODES*NH];
__device__ float g_es[NODES*NE];
__device__ float g_esW[NODES*NZ];
__device__ float g_b0[NZ];
__device__ __half g_Wz[256*NZ];          // [k][n], fp16 (B operand, single)
__device__ float g_c[NODES*NH];

// ---------------- helpers ----------------
__device__ __forceinline__ uint32_t smem_u32(const void* p) {
    uint32_t a;
    asm("{ .reg .u64 t; cvta.to.shared.u64 t, %1; cvt.u32.u64 %0, t; }" : "=r"(a) : "l"(p));
    return a;
}
__device__ __forceinline__ void ldsm4(uint32_t* r, uint32_t addr) {
    asm volatile("ldmatrix.sync.aligned.m8n8.x4.shared.b16 {%0,%1,%2,%3}, [%4];"
        : "=r"(r[0]), "=r"(r[1]), "=r"(r[2]), "=r"(r[3]) : "r"(addr));
}
__device__ __forceinline__ void ldsm4t(uint32_t* r, uint32_t addr) {
    asm volatile("ldmatrix.sync.aligned.m8n8.x4.trans.shared.b16 {%0,%1,%2,%3}, [%4];"
        : "=r"(r[0]), "=r"(r[1]), "=r"(r[2]), "=r"(r[3]) : "r"(addr));
}
__device__ __forceinline__ void mma_f16(float* d, const uint32_t* a, const uint32_t* b) {
    asm volatile("mma.sync.aligned.m16n8k16.row.col.f32.f16.f16.f32 "
        "{%0,%1,%2,%3}, {%4,%5,%6,%7}, {%8,%9}, {%0,%1,%2,%3};"
        : "+f"(d[0]), "+f"(d[1]), "+f"(d[2]), "+f"(d[3])
        : "r"(a[0]), "r"(a[1]), "r"(a[2]), "r"(a[3]), "r"(b[0]), "r"(b[1]));
}
__device__ __forceinline__ void split_h(float x, __half& h, __half& l) {
    h = __float2half_rn(x);
    l = __float2half_rn(x - __half2float(h));
}
__device__ __forceinline__ float sigf(float x) { return 1.f / (1.f + __expf(-x)); }

// ---------------- setup kernels ----------------
__global__ void k_dinv(const float* __restrict__ A) {
    int row = blockIdx.x;
    const float* ap = A + (size_t)row * NN;
    float s = 0.f;
    for (int i = threadIdx.x; i < NN; i += 128) s += ap[i];
    __shared__ float red[4];
    for (int o = 16; o; o >>= 1) s += __shfl_xor_sync(0xffffffffu, s, o);
    if ((threadIdx.x & 31) == 0) red[threadIdx.x >> 5] = s;
    __syncthreads();
    if (threadIdx.x == 0) {
        float d = red[0] + red[1] + red[2] + red[3];
        g_dinv[row] = d > 0.f ? rsqrtf(d) : 0.f;
    }
}

__global__ void k_an(const float* __restrict__ A) {
    int idx = blockIdx.x * 256 + threadIdx.x;
    int b = idx / (NN * NN);
    int r = (idx / NN) % NN;
    int m = idx % NN;
    float v = A[idx] * g_dinv[b * NN + r] * g_dinv[b * NN + m];
    split_h(v, g_An_hi[idx], g_An_lo[idx]);
}

__global__ void k_es(const float* __restrict__ X, const float* __restrict__ Wse,
                     const float* __restrict__ bse, float* __restrict__ out) {
    int idx = blockIdx.x * 256 + threadIdx.x;
    int node = idx >> 7, j = idx & 127;
    const float* x0 = X + (size_t)node * TT * NIN;
    float acc = bse[j];
    #pragma unroll
    for (int q = 0; q < NIN; q++) acc += x0[q] * Wse[q * NE + j];
    g_es[idx] = acc;
    if (j < NIN) out[(size_t)node * TT * NIN + j] = x0[j];
}

__global__ void k_wz(const float* __restrict__ Wpe, const float* __restrict__ bpe,
    const float* __restrict__ Wii, const float* __restrict__ bii,
    const float* __restrict__ Whi, const float* __restrict__ bhi,
    const float* __restrict__ Wif, const float* __restrict__ bif,
    const float* __restrict__ Whf, const float* __restrict__ bhf,
    const float* __restrict__ Wig, const float* __restrict__ big,
    const float* __restrict__ Whg, const float* __restrict__ bhg,
    const float* __restrict__ Wio, const float* __restrict__ bio,
    const float* __restrict__ Who, const float* __restrict__ bho) {
    int idx = blockIdx.x * 256 + threadIdx.x;   // [k][n]
    int k = idx >> 9, n = idx & 511;
    int ch = n >> 2, g = n & 3;
    const float* Wg  = g == 0 ? Wii : g == 1 ? Wif : g == 2 ? Wig : Wio;
    const float* Whx = g == 0 ? Whi : g == 1 ? Whf : g == 2 ? Whg : Who;
    float v;
    if (k < 128) {
        v = 0.f;
        for (int p = 0; p < NE; p++) v += Wpe[k * NE + p] * Wg[(NE + p) * NH + ch];
    } else {
        v = Whx[(k - 128) * NH + ch];
    }
    g_Wz[idx] = __float2half_rn(v);
    if (k == 0) {
        const float* bg  = g == 0 ? bii : g == 1 ? bif : g == 2 ? big : bio;
        const float* bhx = g == 0 ? bhi : g == 1 ? bhf : g == 2 ? bhg : bho;
        float bv = bg[ch] + bhx[ch];
        for (int p = 0; p < NE; p++) bv += bpe[p] * Wg[(NE + p) * NH + ch];
        g_b0[n] = bv;
    }
}

__global__ void k_esw(const float* __restrict__ Wii, const float* __restrict__ Wif,
                      const float* __restrict__ Wig, const float* __restrict__ Wio) {
    int idx = blockIdx.x * 256 + threadIdx.x;
    int node = idx >> 9, j = idx & 511;
    int ch = j >> 2, g = j & 3;
    const float* Wg = g == 0 ? Wii : g == 1 ? Wif : g == 2 ? Wig : Wio;
    const float* e = g_es + (size_t)node * NE;
    float acc = g_b0[j];
    for (int p = 0; p < NE; p++) acc += e[p] * Wg[p * NH + ch];
    g_esW[idx] = acc;
}

__global__ void k_zero() {
    int idx = blockIdx.x * 256 + threadIdx.x;
    g_c[idx] = 0.f;
    __half z = __float2half(0.f);
    g_h_hi[0][idx] = z;
    g_h_lo[0][idx] = z;
}

// ---------------- smem layout (bytes) ----------------
#define S_HH_HI   0u
#define S_HH_LO   16896u
#define S_PIPE    33792u
#define PA_ANH    0u
#define PA_ANL    8704u
#define PA_HCH    17408u
#define S_ZB      86016u      // [32][260] f32
#define S_HN      119296u     // [32][132] f32
#define S_SC      136192u     // [32][132] f32
#define SMEM_TOT  153088

// ---------------- fused per-step kernel ----------------
// grid 128 (node tiles of 32), block 256 (8 warps)
__global__ __launch_bounds__(256, 1) void k_step(int t, const float* __restrict__ Wout,
                                                 const float* __restrict__ bout,
                                                 float* __restrict__ out) {
    extern __shared__ char sm[];
    uint32_t smb = smem_u32(sm);
    int tid = threadIdx.x, lane = tid & 31, w = tid >> 5;
    long node0 = (long)blockIdx.x * 32;
    int b = (int)(node0 >> 9);
    int pp = (t + 1) & 1, pn = t & 1;
    const __half* hp_hi = g_h_hi[pp];
    const __half* hp_lo = g_h_lo[pp];

    int a_r = (lane & 7) + ((lane >> 3) & 1) * 8;   // A x4
    int a_c = ((lane >> 4) & 1) * 8;
    int bt_r = lane & 15;                           // B x4.trans
    int bt_c = ((lane >> 4) & 1) * 8;
    int wm = w >> 2, wn = w & 3;

    // ---- own h rows -> HH cols 128-255 (hi/lo); c state -> sc ----
    {
        #pragma unroll
        for (int i = 0; i < 2; i++) {
            int idx = i * 256 + tid;
            int row = idx >> 4, seg = idx & 15;
            const uint4* sH = (const uint4*)(hp_hi + (node0 + row) * NH) + seg;
            const uint4* sL = (const uint4*)(hp_lo + (node0 + row) * NH) + seg;
            *(uint4*)(sm + S_HH_HI + (row * 264 + 128 + seg * 8) * 2) = *sH;
            *(uint4*)(sm + S_HH_LO + (row * 264 + 128 + seg * 8) * 2) = *sL;
        }
        float* sc = (float*)(sm + S_SC);
        #pragma unroll
        for (int i = 0; i < 4; i++) {
            int idx = i * 256 + tid;
            int row = idx >> 5, c4 = (idx & 31) * 4;
            *(float4*)(sc + row * 132 + c4) = *(const float4*)(g_c + (node0 + row) * NH + c4);
        }
    }

    // ---- Phase A: H = An @ h (4 K-chunks of 128) ----
    float accA[4][4];
    #pragma unroll
    for (int nt = 0; nt < 4; nt++)
        #pragma unroll
        for (int q = 0; q < 4; q++) accA[nt][q] = 0.f;

    for (int c = 0; c < 4; c++) {
        __syncthreads();
        #pragma unroll
        for (int i = 0; i < 2; i++) {
            int idx = i * 256 + tid;
            int row = idx >> 4, seg = idx & 15;
            const uint4* sH = (const uint4*)(g_An_hi + (node0 + row) * (long)NN + c * 128) + seg;
            const uint4* sL = (const uint4*)(g_An_lo + (node0 + row) * (long)NN + c * 128) + seg;
            *(uint4*)(sm + S_PIPE + PA_ANH + (row * 136 + seg * 8) * 2) = *sH;
            *(uint4*)(sm + S_PIPE + PA_ANL + (row * 136 + seg * 8) * 2) = *sL;
        }
        #pragma unroll
        for (int i = 0; i < 8; i++) {
            int idx = i * 256 + tid;
            int row = idx >> 4, seg = idx & 15;
            long nsrc = (long)b * NN + c * 128 + row;
            const uint4* sH = (const uint4*)(hp_hi + nsrc * NH) + seg;
            *(uint4*)(sm + S_PIPE + PA_HCH + (row * 136 + seg * 8) * 2) = *sH;
        }
        __syncthreads();
        #pragma unroll
        for (int kk = 0; kk < 8; kk++) {
            uint32_t aH[4], aL[4];
            uint32_t aoff = (uint32_t)(((wm * 16 + a_r) * 136 + kk * 16 + a_c) * 2);
            ldsm4(aH, smb + S_PIPE + PA_ANH + aoff);
            ldsm4(aL, smb + S_PIPE + PA_ANL + aoff);
            uint32_t b0[4], b1[4];
            uint32_t boff0 = (uint32_t)(((kk * 16 + bt_r) * 136 + wn * 32 + bt_c) * 2);
            uint32_t boff1 = (uint32_t)(((kk * 16 + bt_r) * 136 + wn * 32 + 16 + bt_c) * 2);
            ldsm4t(b0, smb + S_PIPE + PA_HCH + boff0);
            ldsm4t(b1, smb + S_PIPE + PA_HCH + boff1);
            // hi pass then lo pass: same-acc reuse distance = 4
            mma_f16(accA[0], aH, b0);
            mma_f16(accA[1], aH, b0 + 2);
            mma_f16(accA[2], aH, b1);
            mma_f16(accA[3], aH, b1 + 2);
            mma_f16(accA[0], aL, b0);
            mma_f16(accA[1], aL, b0 + 2);
            mma_f16(accA[2], aL, b1);
            mma_f16(accA[3], aL, b1 + 2);
        }
    }
    __syncthreads();

    // ---- HH epilogue: split H into cols 0-127 ----
    {
        int r0 = wm * 16 + (lane >> 2), r1 = r0 + 8;
        #pragma unroll
        for (int nt = 0; nt < 4; nt++) {
            int col = wn * 32 + (nt >> 1) * 16 + (nt & 1) * 8 + (lane & 3) * 2;
            __half h0, l0, h1, l1;
            split_h(accA[nt][0], h0, l0); split_h(accA[nt][1], h1, l1);
            __half2 ph; ph.x = h0; ph.y = h1;
            __half2 pl; pl.x = l0; pl.y = l1;
            *(__half2*)(sm + S_HH_HI + (r0 * 264 + col) * 2) = ph;
            *(__half2*)(sm + S_HH_LO + (r0 * 264 + col) * 2) = pl;
            split_h(accA[nt][2], h0, l0); split_h(accA[nt][3], h1, l1);
            ph.x = h0; ph.y = h1; pl.x = l0; pl.y = l1;
            *(__half2*)(sm + S_HH_HI + (r1 * 264 + col) * 2) = ph;
            *(__half2*)(sm + S_HH_LO + (r1 * 264 + col) * 2) = pl;
        }
    }

    // ---- Phase B: z = esW + [H|h] @ Wz ----
    float* zb = (float*)(sm + S_ZB);
    float* hn = (float*)(sm + S_HN);
    float* sc = (float*)(sm + S_SC);
    float accB[8][4];
    #pragma unroll
    for (int nt = 0; nt < 8; nt++)
        #pragma unroll
        for (int q = 0; q < 4; q++) accB[nt][q] = 0.f;

    for (int nc = 0; nc < 2; nc++) {
        for (int kc = 0; kc < 4; kc++) {
            __syncthreads();
            #pragma unroll
            for (int i = 0; i < 8; i++) {
                int idx = i * 256 + tid;
                int row = idx >> 5, seg = idx & 31;
                long src = (long)(kc * 64 + row) * NZ + nc * 256 + seg * 8;
                *(uint4*)(sm + S_PIPE + (row * 264 + seg * 8) * 2) =
                    *(const uint4*)(g_Wz + src);
            }
            __syncthreads();
            #pragma unroll
            for (int kk = 0; kk < 4; kk++) {
                uint32_t aH[4], aL[4];
                uint32_t aoff = (uint32_t)(((wm * 16 + a_r) * 264 + kc * 64 + kk * 16 + a_c) * 2);
                ldsm4(aH, smb + S_HH_HI + aoff);
                ldsm4(aL, smb + S_HH_LO + aoff);
                uint32_t bf[4][4];
                #pragma unroll
                for (int p = 0; p < 4; p++) {
                    uint32_t boff = (uint32_t)(((kk * 16 + bt_r) * 264 + wn * 64 + p * 16 + bt_c) * 2);
                    ldsm4t(bf[p], smb + S_PIPE + boff);
                }
                // hi pass then lo pass: same-acc reuse distance = 8
                #pragma unroll
                for (int p = 0; p < 4; p++) {
                    mma_f16(accB[2 * p],     aH, bf[p]);
                    mma_f16(accB[2 * p + 1], aH, bf[p] + 2);
                }
                #pragma unroll
                for (int p = 0; p < 4; p++) {
                    mma_f16(accB[2 * p],     aL, bf[p]);
                    mma_f16(accB[2 * p + 1], aL, bf[p] + 2);
                }
            }
        }
        __syncthreads();
        // accums -> zb
        {
            int r0 = wm * 16 + (lane >> 2), r1 = r0 + 8;
            #pragma unroll
            for (int nt = 0; nt < 8; nt++) {
                int col = wn * 64 + (nt >> 1) * 16 + (nt & 1) * 8 + (lane & 3) * 2;
                zb[r0 * 260 + col]     = accB[nt][0];
                zb[r0 * 260 + col + 1] = accB[nt][1];
                zb[r1 * 260 + col]     = accB[nt][2];
                zb[r1 * 260 + col + 1] = accB[nt][3];
                #pragma unroll
                for (int q = 0; q < 4; q++) accB[nt][q] = 0.f;
            }
        }
        __syncthreads();
        // gates
        {
            int row = tid >> 3, g8 = tid & 7;
            long node = node0 + row;
            #pragma unroll
            for (int q = 0; q < 8; q++) {
                int ch = nc * 64 + q * 8 + g8;
                int colz = q * 32 + g8 * 4;
                float4 z4 = *(const float4*)(zb + row * 260 + colz);
                float4 e4 = *(const float4*)(g_esW + node * NZ + nc * 256 + colz);
                float it = sigf(z4.x + e4.x);
                float ft = sigf(z4.y + e4.y);
                float gt = tanhf(z4.z + e4.z);
                float ot = sigf(z4.w + e4.w);
                float cn = ft * sc[row * 132 + ch] + it * gt;
                float hv = ot * tanhf(cn);
                sc[row * 132 + ch] = cn;
                hn[row * 132 + ch] = hv;
            }
        }
        __syncthreads();
    }

    // ---- coalesced c / h writeback ----
    {
        __half* hw_hi = g_h_hi[pn];
        __half* hw_lo = g_h_lo[pn];
        #pragma unroll
        for (int i = 0; i < 4; i++) {
            int idx = i * 256 + tid;
            int row = idx >> 5, c4 = (idx & 31) * 4;
            long base = (node0 + row) * NH + c4;
            *(float4*)(g_c + base) = *(const float4*)(sc + row * 132 + c4);
            float4 hv4 = *(const float4*)(hn + row * 132 + c4);
            __half hh[4], hl[4];
            split_h(hv4.x, hh[0], hl[0]); split_h(hv4.y, hh[1], hl[1]);
            split_h(hv4.z, hh[2], hl[2]); split_h(hv4.w, hh[3], hl[3]);
            *(uint2*)(hw_hi + base) = *(const uint2*)hh;
            *(uint2*)(hw_lo + base) = *(const uint2*)hl;
        }
    }

    // ---- Phase C: out[t] = out[t-1] + h_new @ Wout + bout (exact fp32) ----
    float* wo = (float*)(sm + S_PIPE);
    #pragma unroll
    for (int i = 0; i < 8; i++) {
        int idx = i * 256 + tid;
        int row = idx >> 4, c4 = (idx & 15) * 4;
        *(float4*)(wo + row * 68 + c4) = *(const float4*)(Wout + row * NIN + c4);
    }
    __syncthreads();
    {
        int row = tid >> 3, c8 = (tid & 7) * 8;
        long node = node0 + row;
        float o[8];
        *(float4*)(o)     = *(const float4*)(bout + c8);
        *(float4*)(o + 4) = *(const float4*)(bout + c8 + 4);
        #pragma unroll 4
        for (int k = 0; k < NH; k++) {
            float hv = hn[row * 132 + k];
            float4 w0 = *(const float4*)(wo + k * 68 + c8);
            float4 w1 = *(const float4*)(wo + k * 68 + c8 + 4);
            o[0] += hv * w0.x; o[1] += hv * w0.y;
            o[2] += hv * w0.z; o[3] += hv * w0.w;
            o[4] += hv * w1.x; o[5] += hv * w1.y;
            o[6] += hv * w1.z; o[7] += hv * w1.w;
        }
        long pb = (node * TT + (t - 1)) * NIN + c8;
        long ob = (node * TT + t) * NIN + c8;
        float4 p0 = *(const float4*)(out + pb);
        float4 p1 = *(const float4*)(out + pb + 4);
        float4 w0 = make_float4(p0.x + o[0], p0.y + o[1], p0.z + o[2], p0.w + o[3]);
        float4 w1 = make_float4(p1.x + o[4], p1.y + o[5], p1.z + o[6], p1.w + o[7]);
        *(float4*)(out + ob)     = w0;
        *(float4*)(out + ob + 4) = w1;
    }
}

// ---------------- launch ----------------
extern "C" void kernel_launch(void* const* d_in, const int* in_sizes, int n_in,
                              void* d_out, int out_size) {
    (void)in_sizes; (void)n_in; (void)out_size;
    const float* X    = (const float*)d_in[0];
    const float* A    = (const float*)d_in[1];
    const float* Wse  = (const float*)d_in[2];
    const float* bse  = (const float*)d_in[3];
    const float* Wpe  = (const float*)d_in[4];
    const float* bpe  = (const float*)d_in[5];
    const float* Wii  = (const float*)d_in[6];
    const float* bii  = (const float*)d_in[7];
    const float* Whi  = (const float*)d_in[8];
    const float* bhi  = (const float*)d_in[9];
    const float* Wif  = (const float*)d_in[10];
    const float* bif  = (const float*)d_in[11];
    const float* Whf  = (const float*)d_in[12];
    const float* bhf  = (const float*)d_in[13];
    const float* Wig  = (const float*)d_in[14];
    const float* big  = (const float*)d_in[15];
    const float* Whg  = (const float*)d_in[16];
    const float* bhg  = (const float*)d_in[17];
    const float* Wio  = (const float*)d_in[18];
    const float* bio  = (const float*)d_in[19];
    const float* Who  = (const float*)d_in[20];
    const float* bho  = (const float*)d_in[21];
    const float* Wout = (const float*)d_in[22];
    const float* bout = (const float*)d_in[23];
    float* out = (float*)d_out;

    cudaFuncSetAttribute(k_step, cudaFuncAttributeMaxDynamicSharedMemorySize, SMEM_TOT);

    k_dinv<<<BB * NN, 128>>>(A);
    k_an<<<(BB * NN * NN) / 256, 256>>>(A);
    k_es<<<(NODES * NE) / 256, 256>>>(X, Wse, bse, out);
    k_wz<<<(256 * NZ) / 256, 256>>>(Wpe, bpe, Wii, bii, Whi, bhi, Wif, bif,
                                    Whf, bhf, Wig, big, Whg, bhg,
                                    Wio, bio, Who, bho);
    k_esw<<<(NODES * NZ) / 256, 256>>>(Wii, Wif, Wig, Wio);
    k_zero<<<(NODES * NH) / 256, 256>>>();

    for (int t = 1; t < TT; t++) {
        k_step<<<128, 256, SMEM_TOT>>>(t, Wout, bout, out);
    }
}

// round 10
// speedup vs baseline: 1.5119x; 1.2165x over previous
#include <cuda_runtime.h>
#include <cuda_fp16.h>
#include <math.h>
#include <stdint.h>

#define BB 8
#define NN 512
#define TT 64
#define NIN 64
#define NE 128
#define NH 128
#define NZ 512
#define NODES (BB*NN)   // 4096

// ---------------- persistent device scratch ----------------
__device__ float g_dinv[BB*NN];
__device__ __half g_An_hi[BB*NN*NN], g_An_lo[BB*NN*NN];
__device__ __half g_h_hi[2][NODES*NH], g_h_lo[2][NODES*NH];
__device__ float g_es[NODES*NE];
__device__ float g_esW[NODES*NZ];
__device__ float g_b0[NZ];
__device__ __half g_Wz[256*NZ];          // [k][n], fp16
__device__ float g_c[NODES*NH];

// ---------------- helpers ----------------
__device__ __forceinline__ uint32_t smem_u32(const void* p) {
    uint32_t a;
    asm("{ .reg .u64 t; cvta.to.shared.u64 t, %1; cvt.u32.u64 %0, t; }" : "=r"(a) : "l"(p));
    return a;
}
__device__ __forceinline__ void ldsm4(uint32_t* r, uint32_t addr) {
    asm volatile("ldmatrix.sync.aligned.m8n8.x4.shared.b16 {%0,%1,%2,%3}, [%4];"
        : "=r"(r[0]), "=r"(r[1]), "=r"(r[2]), "=r"(r[3]) : "r"(addr));
}
__device__ __forceinline__ void ldsm4t(uint32_t* r, uint32_t addr) {
    asm volatile("ldmatrix.sync.aligned.m8n8.x4.trans.shared.b16 {%0,%1,%2,%3}, [%4];"
        : "=r"(r[0]), "=r"(r[1]), "=r"(r[2]), "=r"(r[3]) : "r"(addr));
}
__device__ __forceinline__ void mma_f16(float* d, const uint32_t* a, const uint32_t* b) {
    asm volatile("mma.sync.aligned.m16n8k16.row.col.f32.f16.f16.f32 "
        "{%0,%1,%2,%3}, {%4,%5,%6,%7}, {%8,%9}, {%0,%1,%2,%3};"
        : "+f"(d[0]), "+f"(d[1]), "+f"(d[2]), "+f"(d[3])
        : "r"(a[0]), "r"(a[1]), "r"(a[2]), "r"(a[3]), "r"(b[0]), "r"(b[1]));
}
__device__ __forceinline__ void split_h(float x, __half& h, __half& l) {
    h = __float2half_rn(x);
    l = __float2half_rn(x - __half2float(h));
}
__device__ __forceinline__ float sigf(float x) { return 1.f / (1.f + __expf(-x)); }

// ---------------- setup kernels ----------------
__global__ void k_dinv(const float* __restrict__ A) {
    int row = blockIdx.x;
    const float* ap = A + (size_t)row * NN;
    float s = 0.f;
    for (int i = threadIdx.x; i < NN; i += 128) s += ap[i];
    __shared__ float red[4];
    for (int o = 16; o; o >>= 1) s += __shfl_xor_sync(0xffffffffu, s, o);
    if ((threadIdx.x & 31) == 0) red[threadIdx.x >> 5] = s;
    __syncthreads();
    if (threadIdx.x == 0) {
        float d = red[0] + red[1] + red[2] + red[3];
        g_dinv[row] = d > 0.f ? rsqrtf(d) : 0.f;
    }
}

__global__ void k_an(const float* __restrict__ A) {
    int idx = blockIdx.x * 256 + threadIdx.x;
    int b = idx / (NN * NN);
    int r = (idx / NN) % NN;
    int m = idx % NN;
    float v = A[idx] * g_dinv[b * NN + r] * g_dinv[b * NN + m];
    split_h(v, g_An_hi[idx], g_An_lo[idx]);
}

__global__ void k_es(const float* __restrict__ X, const float* __restrict__ Wse,
                     const float* __restrict__ bse, float* __restrict__ out) {
    int idx = blockIdx.x * 256 + threadIdx.x;
    int node = idx >> 7, j = idx & 127;
    const float* x0 = X + (size_t)node * TT * NIN;
    float acc = bse[j];
    #pragma unroll
    for (int q = 0; q < NIN; q++) acc += x0[q] * Wse[q * NE + j];
    g_es[idx] = acc;
    if (j < NIN) out[(size_t)node * TT * NIN + j] = x0[j];
}

__global__ void k_wz(const float* __restrict__ Wpe, const float* __restrict__ bpe,
    const float* __restrict__ Wii, const float* __restrict__ bii,
    const float* __restrict__ Whi, const float* __restrict__ bhi,
    const float* __restrict__ Wif, const float* __restrict__ bif,
    const float* __restrict__ Whf, const float* __restrict__ bhf,
    const float* __restrict__ Wig, const float* __restrict__ big,
    const float* __restrict__ Whg, const float* __restrict__ bhg,
    const float* __restrict__ Wio, const float* __restrict__ bio,
    const float* __restrict__ Who, const float* __restrict__ bho) {
    int idx = blockIdx.x * 256 + threadIdx.x;   // [k][n]
    int k = idx >> 9, n = idx & 511;
    int ch = n >> 2, g = n & 3;
    const float* Wg  = g == 0 ? Wii : g == 1 ? Wif : g == 2 ? Wig : Wio;
    const float* Whx = g == 0 ? Whi : g == 1 ? Whf : g == 2 ? Whg : Who;
    float v;
    if (k < 128) {
        v = 0.f;
        for (int p = 0; p < NE; p++) v += Wpe[k * NE + p] * Wg[(NE + p) * NH + ch];
    } else {
        v = Whx[(k - 128) * NH + ch];
    }
    g_Wz[idx] = __float2half_rn(v);
    if (k == 0) {
        const float* bg  = g == 0 ? bii : g == 1 ? bif : g == 2 ? big : bio;
        const float* bhx = g == 0 ? bhi : g == 1 ? bhf : g == 2 ? bhg : bho;
        float bv = bg[ch] + bhx[ch];
        for (int p = 0; p < NE; p++) bv += bpe[p] * Wg[(NE + p) * NH + ch];
        g_b0[n] = bv;
    }
}

__global__ void k_esw(const float* __restrict__ Wii, const float* __restrict__ Wif,
                      const float* __restrict__ Wig, const float* __restrict__ Wio) {
    int idx = blockIdx.x * 256 + threadIdx.x;
    int node = idx >> 9, j = idx & 511;
    int ch = j >> 2, g = j & 3;
    const float* Wg = g == 0 ? Wii : g == 1 ? Wif : g == 2 ? Wig : Wio;
    const float* e = g_es + (size_t)node * NE;
    float acc = g_b0[j];
    for (int p = 0; p < NE; p++) acc += e[p] * Wg[p * NH + ch];
    g_esW[idx] = acc;
}

__global__ void k_zero() {
    int idx = blockIdx.x * 256 + threadIdx.x;
    g_c[idx] = 0.f;
    __half z = __float2half(0.f);
    g_h_hi[0][idx] = z;
    g_h_lo[0][idx] = z;
}

// ---------------- smem layout (bytes) ----------------
#define S_HH_HI   0u
#define S_HH_LO   16896u
#define S_PIPE    33792u
#define PA_ANH    0u
#define PA_ANL    8704u
#define PA_HCH    17408u
#define WB(s)     (S_PIPE + (s) * 33792u)    // W tile [64][264] fp16, double-buffered
#define S_ZB      101376u     // [32][260] f32
#define S_HN      134656u     // [32][132] f32
#define S_SC      151552u     // [32][132] f32
#define SMEM_TOT  168448

// ---------------- fused per-step kernel ----------------
// grid 128 (node tiles of 32), block 512 (16 warps; 4/SMSP)
__global__ __launch_bounds__(512, 1) void k_step(int t, const float* __restrict__ Wout,
                                                 const float* __restrict__ bout,
                                                 float* __restrict__ out) {
    extern __shared__ char sm[];
    uint32_t smb = smem_u32(sm);
    int tid = threadIdx.x, lane = tid & 31, w = tid >> 5;
    long node0 = (long)blockIdx.x * 32;
    int b = (int)(node0 >> 9);
    int pp = (t + 1) & 1, pn = t & 1;
    const __half* hp_hi = g_h_hi[pp];
    const __half* hp_lo = g_h_lo[pp];

    int a_r = (lane & 7) + ((lane >> 3) & 1) * 8;   // A x4
    int a_c = ((lane >> 4) & 1) * 8;
    int bt_r = lane & 15;                           // B x4.trans
    int bt_c = ((lane >> 4) & 1) * 8;
    int wm = w >> 3, wn = w & 7;                    // 2 m-strips x 8 n-strips

    // ---- own h rows -> HH cols 128-255; c state -> sc ----
    {
        int row = tid >> 4, seg = tid & 15;
        const uint4* sH = (const uint4*)(hp_hi + (node0 + row) * NH) + seg;
        const uint4* sL = (const uint4*)(hp_lo + (node0 + row) * NH) + seg;
        *(uint4*)(sm + S_HH_HI + (row * 264 + 128 + seg * 8) * 2) = *sH;
        *(uint4*)(sm + S_HH_LO + (row * 264 + 128 + seg * 8) * 2) = *sL;
        float* sc = (float*)(sm + S_SC);
        #pragma unroll
        for (int i = 0; i < 2; i++) {
            int idx = i * 512 + tid;
            int r2 = idx >> 5, c4 = (idx & 31) * 4;
            *(float4*)(sc + r2 * 132 + c4) = *(const float4*)(g_c + (node0 + r2) * NH + c4);
        }
    }

    // ---- Phase A: H = An @ h (4 K-chunks of 128; reg-staged next chunk) ----
    float accA[2][4];
    #pragma unroll
    for (int nt = 0; nt < 2; nt++)
        #pragma unroll
        for (int q = 0; q < 4; q++) accA[nt][q] = 0.f;

    {   // store chunk 0
        int row = tid >> 4, seg = tid & 15;
        *(uint4*)(sm + S_PIPE + PA_ANH + (row * 136 + seg * 8) * 2) =
            *((const uint4*)(g_An_hi + (node0 + row) * (long)NN) + seg);
        *(uint4*)(sm + S_PIPE + PA_ANL + (row * 136 + seg * 8) * 2) =
            *((const uint4*)(g_An_lo + (node0 + row) * (long)NN) + seg);
        #pragma unroll
        for (int i = 0; i < 4; i++) {
            int idx = i * 512 + tid;
            int hr = idx >> 4, hs = idx & 15;
            *(uint4*)(sm + S_PIPE + PA_HCH + (hr * 136 + hs * 8) * 2) =
                *((const uint4*)(hp_hi + ((long)b * NN + hr) * NH) + hs);
        }
    }
    __syncthreads();

    for (int c = 0; c < 4; c++) {
        // stage chunk c+1 into registers (LDG overlaps MMA below)
        uint4 sAnH, sAnL, sh[4];
        int row = tid >> 4, seg = tid & 15;
        if (c < 3) {
            sAnH = *((const uint4*)(g_An_hi + (node0 + row) * (long)NN + (c + 1) * 128) + seg);
            sAnL = *((const uint4*)(g_An_lo + (node0 + row) * (long)NN + (c + 1) * 128) + seg);
            #pragma unroll
            for (int i = 0; i < 4; i++) {
                int idx = i * 512 + tid;
                int hr = idx >> 4, hs = idx & 15;
                sh[i] = *((const uint4*)(hp_hi + ((long)b * NN + (c + 1) * 128 + hr) * NH) + hs);
            }
        }
        #pragma unroll
        for (int kk = 0; kk < 8; kk++) {
            uint32_t aH[4], aL[4], b0[4];
            uint32_t aoff = (uint32_t)(((wm * 16 + a_r) * 136 + kk * 16 + a_c) * 2);
            ldsm4(aH, smb + S_PIPE + PA_ANH + aoff);
            ldsm4(aL, smb + S_PIPE + PA_ANL + aoff);
            uint32_t boff = (uint32_t)(((kk * 16 + bt_r) * 136 + wn * 16 + bt_c) * 2);
            ldsm4t(b0, smb + S_PIPE + PA_HCH + boff);
            mma_f16(accA[0], aH, b0);
            mma_f16(accA[1], aH, b0 + 2);
            mma_f16(accA[0], aL, b0);
            mma_f16(accA[1], aL, b0 + 2);
        }
        __syncthreads();
        if (c < 3) {
            *(uint4*)(sm + S_PIPE + PA_ANH + (row * 136 + seg * 8) * 2) = sAnH;
            *(uint4*)(sm + S_PIPE + PA_ANL + (row * 136 + seg * 8) * 2) = sAnL;
            #pragma unroll
            for (int i = 0; i < 4; i++) {
                int idx = i * 512 + tid;
                int hr = idx >> 4, hs = idx & 15;
                *(uint4*)(sm + S_PIPE + PA_HCH + (hr * 136 + hs * 8) * 2) = sh[i];
            }
            __syncthreads();
        }
    }

    // ---- HH epilogue: split H into cols 0-127 ----
    {
        int r0 = wm * 16 + (lane >> 2), r1 = r0 + 8;
        #pragma unroll
        for (int nt = 0; nt < 2; nt++) {
            int col = wn * 16 + nt * 8 + (lane & 3) * 2;
            __half h0, l0, h1, l1;
            split_h(accA[nt][0], h0, l0); split_h(accA[nt][1], h1, l1);
            __half2 ph; ph.x = h0; ph.y = h1;
            __half2 pl; pl.x = l0; pl.y = l1;
            *(__half2*)(sm + S_HH_HI + (r0 * 264 + col) * 2) = ph;
            *(__half2*)(sm + S_HH_LO + (r0 * 264 + col) * 2) = pl;
            split_h(accA[nt][2], h0, l0); split_h(accA[nt][3], h1, l1);
            ph.x = h0; ph.y = h1; pl.x = l0; pl.y = l1;
            *(__half2*)(sm + S_HH_HI + (r1 * 264 + col) * 2) = ph;
            *(__half2*)(sm + S_HH_LO + (r1 * 264 + col) * 2) = pl;
        }
    }

    // ---- Phase B: z = esW + [H|h] @ Wz (8 W tiles, double-buffered + reg-staged) ----
    float* zb = (float*)(sm + S_ZB);
    float* hn = (float*)(sm + S_HN);
    float* sc = (float*)(sm + S_SC);
    float accB[4][4];
    #pragma unroll
    for (int nt = 0; nt < 4; nt++)
        #pragma unroll
        for (int q = 0; q < 4; q++) accB[nt][q] = 0.f;

    {   // store W tile 0 into WB(0)
        #pragma unroll
        for (int i = 0; i < 4; i++) {
            int idx = i * 512 + tid;
            int row = idx >> 5, seg = idx & 31;
            *(uint4*)(sm + WB(0) + (row * 264 + seg * 8) * 2) =
                *(const uint4*)(g_Wz + (long)row * NZ + seg * 8);
        }
    }
    __syncthreads();   // also covers HH epilogue writes

    for (int wt = 0; wt < 8; wt++) {
        int nc = wt >> 2, kc = wt & 3;
        // stage next W tile into registers
        uint4 stg[4];
        if (wt < 7) {
            int n2 = (wt + 1) >> 2, k2 = (wt + 1) & 3;
            #pragma unroll
            for (int i = 0; i < 4; i++) {
                int idx = i * 512 + tid;
                int row = idx >> 5, seg = idx & 31;
                stg[i] = *(const uint4*)(g_Wz + (long)(k2 * 64 + row) * NZ + n2 * 256 + seg * 8);
            }
        }
        uint32_t wb = smb + WB(wt & 1);
        #pragma unroll
        for (int kk = 0; kk < 4; kk++) {
            uint32_t aH[4], aL[4];
            uint32_t aoff = (uint32_t)(((wm * 16 + a_r) * 264 + kc * 64 + kk * 16 + a_c) * 2);
            ldsm4(aH, smb + S_HH_HI + aoff);
            ldsm4(aL, smb + S_HH_LO + aoff);
            uint32_t bf[2][4];
            #pragma unroll
            for (int p = 0; p < 2; p++) {
                uint32_t boff = (uint32_t)(((kk * 16 + bt_r) * 264 + wn * 32 + p * 16 + bt_c) * 2);
                ldsm4t(bf[p], wb + boff);
            }
            mma_f16(accB[0], aH, bf[0]);
            mma_f16(accB[1], aH, bf[0] + 2);
            mma_f16(accB[2], aH, bf[1]);
            mma_f16(accB[3], aH, bf[1] + 2);
            mma_f16(accB[0], aL, bf[0]);
            mma_f16(accB[1], aL, bf[0] + 2);
            mma_f16(accB[2], aL, bf[1]);
            mma_f16(accB[3], aL, bf[1] + 2);
        }
        if (wt < 7) {
            uint32_t wb2 = smb + WB((wt + 1) & 1);
            #pragma unroll
            for (int i = 0; i < 4; i++) {
                int idx = i * 512 + tid;
                int row = idx >> 5, seg = idx & 31;
                *(uint4*)(sm + (wb2 - smb) + (row * 264 + seg * 8) * 2) = stg[i];
            }
        }
        __syncthreads();

        if (kc == 3) {
            // accums -> zb
            {
                int r0 = wm * 16 + (lane >> 2), r1 = r0 + 8;
                #pragma unroll
                for (int nt = 0; nt < 4; nt++) {
                    int col = wn * 32 + nt * 8 + (lane & 3) * 2;
                    zb[r0 * 260 + col]     = accB[nt][0];
                    zb[r0 * 260 + col + 1] = accB[nt][1];
                    zb[r1 * 260 + col]     = accB[nt][2];
                    zb[r1 * 260 + col + 1] = accB[nt][3];
                    #pragma unroll
                    for (int q = 0; q < 4; q++) accB[nt][q] = 0.f;
                }
            }
            __syncthreads();
            // gates: thread = (row = tid>>4, g16 = tid&15), 4 channels each
            {
                int row = tid >> 4, g16 = tid & 15;
                long node = node0 + row;
                #pragma unroll
                for (int q = 0; q < 4; q++) {
                    int ch = nc * 64 + q * 16 + g16;
                    int colz = q * 64 + g16 * 4;
                    float4 z4 = *(const float4*)(zb + row * 260 + colz);
                    float4 e4 = *(const float4*)(g_esW + node * NZ + nc * 256 + colz);
                    float it = sigf(z4.x + e4.x);
                    float ft = sigf(z4.y + e4.y);
                    float gt = tanhf(z4.z + e4.z);
                    float ot = sigf(z4.w + e4.w);
                    float cn = ft * sc[row * 132 + ch] + it * gt;
                    float hv = ot * tanhf(cn);
                    sc[row * 132 + ch] = cn;
                    hn[row * 132 + ch] = hv;
                }
            }
            __syncthreads();
        }
    }

    // ---- coalesced c / h writeback ----
    {
        __half* hw_hi = g_h_hi[pn];
        __half* hw_lo = g_h_lo[pn];
        #pragma unroll
        for (int i = 0; i < 2; i++) {
            int idx = i * 512 + tid;
            int row = idx >> 5, c4 = (idx & 31) * 4;
            long base = (node0 + row) * NH + c4;
            *(float4*)(g_c + base) = *(const float4*)(sc + row * 132 + c4);
            float4 hv4 = *(const float4*)(hn + row * 132 + c4);
            __half hh[4], hl[4];
            split_h(hv4.x, hh[0], hl[0]); split_h(hv4.y, hh[1], hl[1]);
            split_h(hv4.z, hh[2], hl[2]); split_h(hv4.w, hh[3], hl[3]);
            *(uint2*)(hw_hi + base) = *(const uint2*)hh;
            *(uint2*)(hw_lo + base) = *(const uint2*)hl;
        }
    }

    // ---- Phase C: out[t] = out[t-1] + h_new @ Wout + bout (exact fp32) ----
    float* wo = (float*)(sm + S_PIPE);
    for (int idx = tid; idx < 128 * 17; idx += 512) {
        int row = idx / 17, c4 = (idx % 17) * 4;
        if (c4 < NIN)
            *(float4*)(wo + row * 68 + c4) = *(const float4*)(Wout + row * NIN + c4);
    }
    __syncthreads();
    {
        int row = tid >> 4, c4 = (tid & 15) * 4;
        long node = node0 + row;
        float o[4];
        *(float4*)(o) = *(const float4*)(bout + c4);
        #pragma unroll 8
        for (int k = 0; k < NH; k++) {
            float hv = hn[row * 132 + k];
            float4 w0 = *(const float4*)(wo + k * 68 + c4);
            o[0] += hv * w0.x; o[1] += hv * w0.y;
            o[2] += hv * w0.z; o[3] += hv * w0.w;
        }
        long pb = (node * TT + (t - 1)) * NIN + c4;
        long ob = (node * TT + t) * NIN + c4;
        float4 p0 = *(const float4*)(out + pb);
        float4 w0 = make_float4(p0.x + o[0], p0.y + o[1], p0.z + o[2], p0.w + o[3]);
        *(float4*)(out + ob) = w0;
    }
}

// ---------------- launch ----------------
extern "C" void kernel_launch(void* const* d_in, const int* in_sizes, int n_in,
                              void* d_out, int out_size) {
    (void)in_sizes; (void)n_in; (void)out_size;
    const float* X    = (const float*)d_in[0];
    const float* A    = (const float*)d_in[1];
    const float* Wse  = (const float*)d_in[2];
    const float* bse  = (const float*)d_in[3];
    const float* Wpe  = (const float*)d_in[4];
    const float* bpe  = (const float*)d_in[5];
    const float* Wii  = (const float*)d_in[6];
    const float* bii  = (const float*)d_in[7];
    const float* Whi  = (const float*)d_in[8];
    const float* bhi  = (const float*)d_in[9];
    const float* Wif  = (const float*)d_in[10];
    const float* bif  = (const float*)d_in[11];
    const float* Whf  = (const float*)d_in[12];
    const float* bhf  = (const float*)d_in[13];
    const float* Wig  = (const float*)d_in[14];
    const float* big  = (const float*)d_in[15];
    const float* Whg  = (const float*)d_in[16];
    const float* bhg  = (const float*)d_in[17];
    const float* Wio  = (const float*)d_in[18];
    const float* bio  = (const float*)d_in[19];
    const float* Who  = (const float*)d_in[20];
    const float* bho  = (const float*)d_in[21];
    const float* Wout = (const float*)d_in[22];
    const float* bout = (const float*)d_in[23];
    float* out = (float*)d_out;

    cudaFuncSetAttribute(k_step, cudaFuncAttributeMaxDynamicSharedMemorySize, SMEM_TOT);

    k_dinv<<<BB * NN, 128>>>(A);
    k_an<<<(BB * NN * NN) / 256, 256>>>(A);
    k_es<<<(NODES * NE) / 256, 256>>>(X, Wse, bse, out);
    k_wz<<<(256 * NZ) / 256, 256>>>(Wpe, bpe, Wii, bii, Whi, bhi, Wif, bif,
                                    Whf, bhf, Wig, big, Whg, bhg,
                                    Wio, bio, Who, bho);
    k_esw<<<(NODES * NZ) / 256, 256>>>(Wii, Wif, Wig, Wio);
    k_zero<<<(NODES * NH) / 256, 256>>>();

    for (int t = 1; t < TT; t++) {
        k_step<<<128, 512, SMEM_TOT>>>(t, Wout, bout, out);
    }
}

// round 11
// speedup vs baseline: 2.0259x; 1.3399x over previous
#include <cuda_runtime.h>
#include <cuda_fp16.h>
#include <math.h>
#include <stdint.h>

#define BB 8
#define NN 512
#define TT 64
#define NIN 64
#define NE 128
#define NH 128
#define NZ 512
#define NODES (BB*NN)   // 4096

// ---------------- persistent device scratch ----------------
__device__ float g_dinv[BB*NN];
__device__ __half g_An[BB*NN*NN];        // fp16 single
__device__ __half g_h[2][NODES*NH];      // fp16 single, ping-pong
__device__ float g_es[NODES*NE];
__device__ float g_esW[NODES*NZ];
__device__ float g_b0[NZ];
__device__ __half g_Wz[256*NZ];          // [k][n], fp16 single
__device__ __half g_Wo_hi[NH*NIN], g_Wo_lo[NH*NIN];   // [k][n] split fp16
__device__ float g_c[NODES*NH];

// ---------------- helpers ----------------
__device__ __forceinline__ uint32_t smem_u32(const void* p) {
    uint32_t a;
    asm("{ .reg .u64 t; cvta.to.shared.u64 t, %1; cvt.u32.u64 %0, t; }" : "=r"(a) : "l"(p));
    return a;
}
__device__ __forceinline__ void ldsm4(uint32_t* r, uint32_t addr) {
    asm volatile("ldmatrix.sync.aligned.m8n8.x4.shared.b16 {%0,%1,%2,%3}, [%4];"
        : "=r"(r[0]), "=r"(r[1]), "=r"(r[2]), "=r"(r[3]) : "r"(addr));
}
__device__ __forceinline__ void ldsm4t(uint32_t* r, uint32_t addr) {
    asm volatile("ldmatrix.sync.aligned.m8n8.x4.trans.shared.b16 {%0,%1,%2,%3}, [%4];"
        : "=r"(r[0]), "=r"(r[1]), "=r"(r[2]), "=r"(r[3]) : "r"(addr));
}
__device__ __forceinline__ void ldsm2t(uint32_t* r, uint32_t addr) {
    asm volatile("ldmatrix.sync.aligned.m8n8.x2.trans.shared.b16 {%0,%1}, [%2];"
        : "=r"(r[0]), "=r"(r[1]) : "r"(addr));
}
__device__ __forceinline__ void mma_f16(float* d, const uint32_t* a, const uint32_t* b) {
    asm volatile("mma.sync.aligned.m16n8k16.row.col.f32.f16.f16.f32 "
        "{%0,%1,%2,%3}, {%4,%5,%6,%7}, {%8,%9}, {%0,%1,%2,%3};"
        : "+f"(d[0]), "+f"(d[1]), "+f"(d[2]), "+f"(d[3])
        : "r"(a[0]), "r"(a[1]), "r"(a[2]), "r"(a[3]), "r"(b[0]), "r"(b[1]));
}
__device__ __forceinline__ void split_h(float x, __half& h, __half& l) {
    h = __float2half_rn(x);
    l = __float2half_rn(x - __half2float(h));
}
__device__ __forceinline__ float sigf(float x) { return 1.f / (1.f + __expf(-x)); }

// ---------------- setup kernels ----------------
__global__ void k_dinv(const float* __restrict__ A) {
    int row = blockIdx.x;
    const float* ap = A + (size_t)row * NN;
    float s = 0.f;
    for (int i = threadIdx.x; i < NN; i += 128) s += ap[i];
    __shared__ float red[4];
    for (int o = 16; o; o >>= 1) s += __shfl_xor_sync(0xffffffffu, s, o);
    if ((threadIdx.x & 31) == 0) red[threadIdx.x >> 5] = s;
    __syncthreads();
    if (threadIdx.x == 0) {
        float d = red[0] + red[1] + red[2] + red[3];
        g_dinv[row] = d > 0.f ? rsqrtf(d) : 0.f;
    }
}

__global__ void k_an(const float* __restrict__ A) {
    int idx = blockIdx.x * 256 + threadIdx.x;
    int b = idx / (NN * NN);
    int r = (idx / NN) % NN;
    int m = idx % NN;
    float v = A[idx] * g_dinv[b * NN + r] * g_dinv[b * NN + m];
    g_An[idx] = __float2half_rn(v);
}

__global__ void k_es(const float* __restrict__ X, const float* __restrict__ Wse,
                     const float* __restrict__ bse, float* __restrict__ out) {
    int idx = blockIdx.x * 256 + threadIdx.x;
    int node = idx >> 7, j = idx & 127;
    const float* x0 = X + (size_t)node * TT * NIN;
    float acc = bse[j];
    #pragma unroll
    for (int q = 0; q < NIN; q++) acc += x0[q] * Wse[q * NE + j];
    g_es[idx] = acc;
    if (j < NIN) out[(size_t)node * TT * NIN + j] = x0[j];
}

__global__ void k_wz(const float* __restrict__ Wpe, const float* __restrict__ bpe,
    const float* __restrict__ Wii, const float* __restrict__ bii,
    const float* __restrict__ Whi, const float* __restrict__ bhi,
    const float* __restrict__ Wif, const float* __restrict__ bif,
    const float* __restrict__ Whf, const float* __restrict__ bhf,
    const float* __restrict__ Wig, const float* __restrict__ big,
    const float* __restrict__ Whg, const float* __restrict__ bhg,
    const float* __restrict__ Wio, const float* __restrict__ bio,
    const float* __restrict__ Who, const float* __restrict__ bho) {
    int idx = blockIdx.x * 256 + threadIdx.x;   // [k][n]
    int k = idx >> 9, n = idx & 511;
    int ch = n >> 2, g = n & 3;
    const float* Wg  = g == 0 ? Wii : g == 1 ? Wif : g == 2 ? Wig : Wio;
    const float* Whx = g == 0 ? Whi : g == 1 ? Whf : g == 2 ? Whg : Who;
    float v;
    if (k < 128) {
        v = 0.f;
        for (int p = 0; p < NE; p++) v += Wpe[k * NE + p] * Wg[(NE + p) * NH + ch];
    } else {
        v = Whx[(k - 128) * NH + ch];
    }
    g_Wz[idx] = __float2half_rn(v);
    if (k == 0) {
        const float* bg  = g == 0 ? bii : g == 1 ? bif : g == 2 ? big : bio;
        const float* bhx = g == 0 ? bhi : g == 1 ? bhf : g == 2 ? bhg : bho;
        float bv = bg[ch] + bhx[ch];
        for (int p = 0; p < NE; p++) bv += bpe[p] * Wg[(NE + p) * NH + ch];
        g_b0[n] = bv;
    }
}

__global__ void k_esw(const float* __restrict__ Wii, const float* __restrict__ Wif,
                      const float* __restrict__ Wig, const float* __restrict__ Wio) {
    int idx = blockIdx.x * 256 + threadIdx.x;
    int node = idx >> 9, j = idx & 511;
    int ch = j >> 2, g = j & 3;
    const float* Wg = g == 0 ? Wii : g == 1 ? Wif : g == 2 ? Wig : Wio;
    const float* e = g_es + (size_t)node * NE;
    float acc = g_b0[j];
    for (int p = 0; p < NE; p++) acc += e[p] * Wg[p * NH + ch];
    g_esW[idx] = acc;
}

__global__ void k_wo(const float* __restrict__ Wout) {
    int idx = blockIdx.x * 256 + threadIdx.x;   // NH*NIN, [k][n]
    split_h(Wout[idx], g_Wo_hi[idx], g_Wo_lo[idx]);
}

__global__ void k_zero() {
    int idx = blockIdx.x * 256 + threadIdx.x;
    g_c[idx] = 0.f;
    g_h[0][idx] = __float2half(0.f);
}

// ---------------- smem layout (bytes) ----------------
#define S_HH_HI   0u          // [32][264] fp16: GEMM-B A operand; later hn_hi cols 0-127
#define S_HH_LO   16896u      // [32][264] fp16: only cols 0-127 used (hn_lo for phase C)
#define S_PIPE    33792u
#define PA_ANH    0u          // [32][136] fp16
#define PA_HCH    8704u       // [128][136] fp16
#define WB(s)     (S_PIPE + (s) * 33792u)    // phase B W tile [64][264]; phase C Wo hi/lo [128][72]
#define S_ZB      101376u     // [32][260] f32
#define S_HN      134656u     // [32][132] f32
#define S_SC      151552u     // [32][132] f32
#define SMEM_TOT  168448

// ---------------- fused per-step kernel ----------------
// grid 128 (node tiles of 32), block 512 (16 warps; 4/SMSP)
__global__ __launch_bounds__(512, 1) void k_step(int t, const float* __restrict__ bout,
                                                 float* __restrict__ out) {
    extern __shared__ char sm[];
    uint32_t smb = smem_u32(sm);
    int tid = threadIdx.x, lane = tid & 31, w = tid >> 5;
    long node0 = (long)blockIdx.x * 32;
    int b = (int)(node0 >> 9);
    int pp = (t + 1) & 1, pn = t & 1;
    const __half* hp = g_h[pp];

    int a_r = (lane & 7) + ((lane >> 3) & 1) * 8;   // A x4
    int a_c = ((lane >> 4) & 1) * 8;
    int bt_r = lane & 15;                           // B x4.trans
    int bt_c = ((lane >> 4) & 1) * 8;
    int wm = w >> 3, wn = w & 7;                    // 2 m-strips x 8 n-strips

    // ---- own h rows -> HH cols 128-255; c state -> sc ----
    {
        int row = tid >> 4, seg = tid & 15;
        if (seg < 8)   // 32 rows x 128 cols = 512 uint4; only 8 segs of 16B
            ;
        // 32 rows x 16 segs of 8 halves = 512 iterations exactly = 512 threads
        const uint4* sH = (const uint4*)(hp + (node0 + row) * NH) + seg;
        // guard: seg in 0..15 covers 128 halves
        *(uint4*)(sm + S_HH_HI + (row * 264 + 128 + seg * 8) * 2) = *sH;
        float* sc = (float*)(sm + S_SC);
        #pragma unroll
        for (int i = 0; i < 2; i++) {
            int idx = i * 512 + tid;
            int r2 = idx >> 5, c4 = (idx & 31) * 4;
            *(float4*)(sc + r2 * 132 + c4) = *(const float4*)(g_c + (node0 + r2) * NH + c4);
        }
    }

    // ---- Phase A: H = An @ h (4 K-chunks of 128; reg-staged next chunk) ----
    float accA[2][4];
    #pragma unroll
    for (int nt = 0; nt < 2; nt++)
        #pragma unroll
        for (int q = 0; q < 4; q++) accA[nt][q] = 0.f;

    {   // store chunk 0
        int row = tid >> 4, seg = tid & 15;
        if (tid < 512) {
            // An [32][128]: 32 rows x 16 segs -> 512 threads
            *(uint4*)(sm + S_PIPE + PA_ANH + (row * 136 + seg * 8) * 2) =
                *((const uint4*)(g_An + (node0 + row) * (long)NN) + seg);
        }
        #pragma unroll
        for (int i = 0; i < 4; i++) {
            int idx = i * 512 + tid;
            int hr = idx >> 4, hs = idx & 15;
            *(uint4*)(sm + S_PIPE + PA_HCH + (hr * 136 + hs * 8) * 2) =
                *((const uint4*)(hp + ((long)b * NN + hr) * NH) + hs);
        }
    }
    __syncthreads();

    for (int c = 0; c < 4; c++) {
        uint4 sAnH, sh[4];
        int row = tid >> 4, seg = tid & 15;
        if (c < 3) {
            sAnH = *((const uint4*)(g_An + (node0 + row) * (long)NN + (c + 1) * 128) + seg);
            #pragma unroll
            for (int i = 0; i < 4; i++) {
                int idx = i * 512 + tid;
                int hr = idx >> 4, hs = idx & 15;
                sh[i] = *((const uint4*)(hp + ((long)b * NN + (c + 1) * 128 + hr) * NH) + hs);
            }
        }
        #pragma unroll
        for (int kk = 0; kk < 8; kk++) {
            uint32_t aH[4], b0[4];
            uint32_t aoff = (uint32_t)(((wm * 16 + a_r) * 136 + kk * 16 + a_c) * 2);
            ldsm4(aH, smb + S_PIPE + PA_ANH + aoff);
            uint32_t boff = (uint32_t)(((kk * 16 + bt_r) * 136 + wn * 16 + bt_c) * 2);
            ldsm4t(b0, smb + S_PIPE + PA_HCH + boff);
            mma_f16(accA[0], aH, b0);
            mma_f16(accA[1], aH, b0 + 2);
        }
        __syncthreads();
        if (c < 3) {
            *(uint4*)(sm + S_PIPE + PA_ANH + (row * 136 + seg * 8) * 2) = sAnH;
            #pragma unroll
            for (int i = 0; i < 4; i++) {
                int idx = i * 512 + tid;
                int hr = idx >> 4, hs = idx & 15;
                *(uint4*)(sm + S_PIPE + PA_HCH + (hr * 136 + hs * 8) * 2) = sh[i];
            }
            __syncthreads();
        }
    }

    // ---- HH epilogue: H (fp16 single) into HH_HI cols 0-127 ----
    {
        int r0 = wm * 16 + (lane >> 2), r1 = r0 + 8;
        #pragma unroll
        for (int nt = 0; nt < 2; nt++) {
            int col = wn * 16 + nt * 8 + (lane & 3) * 2;
            __half2 ph;
            ph.x = __float2half_rn(accA[nt][0]);
            ph.y = __float2half_rn(accA[nt][1]);
            *(__half2*)(sm + S_HH_HI + (r0 * 264 + col) * 2) = ph;
            ph.x = __float2half_rn(accA[nt][2]);
            ph.y = __float2half_rn(accA[nt][3]);
            *(__half2*)(sm + S_HH_HI + (r1 * 264 + col) * 2) = ph;
        }
    }

    // ---- Phase B: z = esW + [H|h] @ Wz (8 W tiles, double-buffered + reg-staged) ----
    float* zb = (float*)(sm + S_ZB);
    float* hn = (float*)(sm + S_HN);
    float* sc = (float*)(sm + S_SC);
    float accB[4][4];
    #pragma unroll
    for (int nt = 0; nt < 4; nt++)
        #pragma unroll
        for (int q = 0; q < 4; q++) accB[nt][q] = 0.f;

    {   // store W tile 0 into WB(0)
        #pragma unroll
        for (int i = 0; i < 4; i++) {
            int idx = i * 512 + tid;
            int row = idx >> 5, seg = idx & 31;
            *(uint4*)(sm + WB(0) + (row * 264 + seg * 8) * 2) =
                *(const uint4*)(g_Wz + (long)row * NZ + seg * 8);
        }
    }
    __syncthreads();   // covers HH epilogue too

    for (int wt = 0; wt < 8; wt++) {
        int nc = wt >> 2, kc = wt & 3;
        uint4 stg[4];
        if (wt < 7) {
            int n2 = (wt + 1) >> 2, k2 = (wt + 1) & 3;
            #pragma unroll
            for (int i = 0; i < 4; i++) {
                int idx = i * 512 + tid;
                int row = idx >> 5, seg = idx & 31;
                stg[i] = *(const uint4*)(g_Wz + (long)(k2 * 64 + row) * NZ + n2 * 256 + seg * 8);
            }
        }
        uint32_t wbuf = smb + WB(wt & 1);
        #pragma unroll
        for (int kk = 0; kk < 4; kk++) {
            uint32_t aH[4];
            uint32_t aoff = (uint32_t)(((wm * 16 + a_r) * 264 + kc * 64 + kk * 16 + a_c) * 2);
            ldsm4(aH, smb + S_HH_HI + aoff);
            uint32_t bf[2][4];
            #pragma unroll
            for (int p = 0; p < 2; p++) {
                uint32_t boff = (uint32_t)(((kk * 16 + bt_r) * 264 + wn * 32 + p * 16 + bt_c) * 2);
                ldsm4t(bf[p], wbuf + boff);
            }
            mma_f16(accB[0], aH, bf[0]);
            mma_f16(accB[1], aH, bf[0] + 2);
            mma_f16(accB[2], aH, bf[1]);
            mma_f16(accB[3], aH, bf[1] + 2);
        }
        if (wt < 7) {
            uint32_t wb2 = WB((wt + 1) & 1);
            #pragma unroll
            for (int i = 0; i < 4; i++) {
                int idx = i * 512 + tid;
                int row = idx >> 5, seg = idx & 31;
                *(uint4*)(sm + wb2 + (row * 264 + seg * 8) * 2) = stg[i];
            }
        }
        __syncthreads();

        if (kc == 3) {
            {
                int r0 = wm * 16 + (lane >> 2), r1 = r0 + 8;
                #pragma unroll
                for (int nt = 0; nt < 4; nt++) {
                    int col = wn * 32 + nt * 8 + (lane & 3) * 2;
                    zb[r0 * 260 + col]     = accB[nt][0];
                    zb[r0 * 260 + col + 1] = accB[nt][1];
                    zb[r1 * 260 + col]     = accB[nt][2];
                    zb[r1 * 260 + col + 1] = accB[nt][3];
                    #pragma unroll
                    for (int q = 0; q < 4; q++) accB[nt][q] = 0.f;
                }
            }
            __syncthreads();
            {
                int row = tid >> 4, g16 = tid & 15;
                long node = node0 + row;
                #pragma unroll
                for (int q = 0; q < 4; q++) {
                    int ch = nc * 64 + q * 16 + g16;
                    int colz = q * 64 + g16 * 4;
                    float4 z4 = *(const float4*)(zb + row * 260 + colz);
                    float4 e4 = *(const float4*)(g_esW + node * NZ + nc * 256 + colz);
                    float it = sigf(z4.x + e4.x);
                    float ft = sigf(z4.y + e4.y);
                    float gt = tanhf(z4.z + e4.z);
                    float ot = sigf(z4.w + e4.w);
                    float cn = ft * sc[row * 132 + ch] + it * gt;
                    float hv = ot * tanhf(cn);
                    sc[row * 132 + ch] = cn;
                    hn[row * 132 + ch] = hv;
                }
            }
            __syncthreads();
        }
    }

    // ---- writeback c + h(fp16); stage hn split into HH cols 0-127; stage Wo ----
    {
        __half* hw = g_h[pn];
        #pragma unroll
        for (int i = 0; i < 2; i++) {
            int idx = i * 512 + tid;
            int row = idx >> 5, c4 = (idx & 31) * 4;
            long base = (node0 + row) * NH + c4;
            *(float4*)(g_c + base) = *(const float4*)(sc + row * 132 + c4);
            float4 hv4 = *(const float4*)(hn + row * 132 + c4);
            __half hh[4];
            hh[0] = __float2half_rn(hv4.x); hh[1] = __float2half_rn(hv4.y);
            hh[2] = __float2half_rn(hv4.z); hh[3] = __float2half_rn(hv4.w);
            *(uint2*)(hw + base) = *(const uint2*)hh;
        }
        // hn split hi/lo into HH_HI/HH_LO cols 0-127 (A operand for phase C)
        #pragma unroll
        for (int i = 0; i < 4; i++) {
            int idx = i * 512 + tid;
            int row = idx >> 6, c2 = (idx & 63) * 2;
            float hv0 = hn[row * 132 + c2], hv1 = hn[row * 132 + c2 + 1];
            __half h0, l0, h1, l1;
            split_h(hv0, h0, l0); split_h(hv1, h1, l1);
            __half2 ph; ph.x = h0; ph.y = h1;
            __half2 pl; pl.x = l0; pl.y = l1;
            *(__half2*)(sm + S_HH_HI + (row * 264 + c2) * 2) = ph;
            *(__half2*)(sm + S_HH_LO + (row * 264 + c2) * 2) = pl;
        }
        // Wout split tiles [128][72] into WB(0)=hi, WB(1)=lo
        #pragma unroll
        for (int i = 0; i < 2; i++) {
            int idx = i * 512 + tid;
            int row = idx >> 3, seg = idx & 7;
            *(uint4*)(sm + WB(0) + (row * 72 + seg * 8) * 2) =
                *((const uint4*)(g_Wo_hi + row * NIN) + seg);
            *(uint4*)(sm + WB(1) + (row * 72 + seg * 8) * 2) =
                *((const uint4*)(g_Wo_lo + row * NIN) + seg);
        }
    }
    __syncthreads();

    // ---- Phase C: out[t] = out[t-1] + hn @ Wout + bout (3-term split MMA) ----
    {
        float accC[4] = {0.f, 0.f, 0.f, 0.f};
        #pragma unroll
        for (int kk = 0; kk < 8; kk++) {
            uint32_t aH[4], aL[4], bH[2], bL[2];
            uint32_t aoff = (uint32_t)(((wm * 16 + a_r) * 264 + kk * 16 + a_c) * 2);
            ldsm4(aH, smb + S_HH_HI + aoff);
            ldsm4(aL, smb + S_HH_LO + aoff);
            uint32_t boff = (uint32_t)(((kk * 16 + bt_r) * 72 + wn * 8) * 2);
            ldsm2t(bH, smb + WB(0) + boff);
            ldsm2t(bL, smb + WB(1) + boff);
            mma_f16(accC, aH, bH);
            mma_f16(accC, aH, bL);
            mma_f16(accC, aL, bH);
        }
        int r0 = wm * 16 + (lane >> 2), r1 = r0 + 8;
        int col = wn * 8 + (lane & 3) * 2;
        float b0v = bout[col], b1v = bout[col + 1];
        long pb0 = (((node0 + r0) * TT) + (t - 1)) * NIN + col;
        long ob0 = (((node0 + r0) * TT) + t) * NIN + col;
        long pb1 = (((node0 + r1) * TT) + (t - 1)) * NIN + col;
        long ob1 = (((node0 + r1) * TT) + t) * NIN + col;
        float2 p0 = *(const float2*)(out + pb0);
        float2 p1 = *(const float2*)(out + pb1);
        float2 w0 = make_float2(p0.x + accC[0] + b0v, p0.y + accC[1] + b1v);
        float2 w1 = make_float2(p1.x + accC[2] + b0v, p1.y + accC[3] + b1v);
        *(float2*)(out + ob0) = w0;
        *(float2*)(out + ob1) = w1;
    }
}

// ---------------- launch ----------------
extern "C" void kernel_launch(void* const* d_in, const int* in_sizes, int n_in,
                              void* d_out, int out_size) {
    (void)in_sizes; (void)n_in; (void)out_size;
    const float* X    = (const float*)d_in[0];
    const float* A    = (const float*)d_in[1];
    const float* Wse  = (const float*)d_in[2];
    const float* bse  = (const float*)d_in[3];
    const float* Wpe  = (const float*)d_in[4];
    const float* bpe  = (const float*)d_in[5];
    const float* Wii  = (const float*)d_in[6];
    const float* bii  = (const float*)d_in[7];
    const float* Whi  = (const float*)d_in[8];
    const float* bhi  = (const float*)d_in[9];
    const float* Wif  = (const float*)d_in[10];
    const float* bif  = (const float*)d_in[11];
    const float* Whf  = (const float*)d_in[12];
    const float* bhf  = (const float*)d_in[13];
    const float* Wig  = (const float*)d_in[14];
    const float* big  = (const float*)d_in[15];
    const float* Whg  = (const float*)d_in[16];
    const float* bhg  = (const float*)d_in[17];
    const float* Wio  = (const float*)d_in[18];
    const float* bio  = (const float*)d_in[19];
    const float* Who  = (const float*)d_in[20];
    const float* bho  = (const float*)d_in[21];
    const float* Wout = (const float*)d_in[22];
    const float* bout = (const float*)d_in[23];
    float* out = (float*)d_out;

    cudaFuncSetAttribute(k_step, cudaFuncAttributeMaxDynamicSharedMemorySize, SMEM_TOT);

    k_dinv<<<BB * NN, 128>>>(A);
    k_an<<<(BB * NN * NN) / 256, 256>>>(A);
    k_es<<<(NODES * NE) / 256, 256>>>(X, Wse, bse, out);
    k_wz<<<(256 * NZ) / 256, 256>>>(Wpe, bpe, Wii, bii, Whi, bhi, Wif, bif,
                                    Whf, bhf, Wig, big, Whg, bhg,
                                    Wio, bio, Who, bho);
    k_esw<<<(NODES * NZ) / 256, 256>>>(Wii, Wif, Wig, Wio);
    k_wo<<<(NH * NIN) / 256, 256>>>(Wout);
    k_zero<<<(NODES * NH) / 256, 256>>>();

    for (int t = 1; t < TT; t++) {
        k_step<<<128, 512, SMEM_TOT>>>(t, bout, out);
    }
}

// round 13
// speedup vs baseline: 2.0877x; 1.0305x over previous
#include <cuda_runtime.h>
#include <cuda_fp16.h>
#include <math.h>
#include <stdint.h>

#define BB 8
#define NN 512
#define TT 64
#define NIN 64
#define NE 128
#define NH 128
#define NZ 512
#define NODES (BB*NN)   // 4096

// ---------------- persistent device scratch ----------------
__device__ float g_dinv[BB*NN];
__device__ __half g_An[BB*NN*NN];        // fp16 single
__device__ __half g_h[2][NODES*NH];      // fp16 single, ping-pong
__device__ float g_es[NODES*NE];
__device__ float g_esW[NODES*NZ];
__device__ float g_b0[NZ];
__device__ __half g_Wz[256*NZ];          // [k][n], fp16 single
__device__ __half g_Wo_hi[NH*NIN], g_Wo_lo[NH*NIN];   // [k][n] split fp16
__device__ int g_barc;
__device__ int g_barg;

// ---------------- helpers ----------------
__device__ __forceinline__ uint32_t smem_u32(const void* p) {
    uint32_t a;
    asm("{ .reg .u64 t; cvta.to.shared.u64 t, %1; cvt.u32.u64 %0, t; }" : "=r"(a) : "l"(p));
    return a;
}
__device__ __forceinline__ void ldsm4(uint32_t* r, uint32_t addr) {
    asm volatile("ldmatrix.sync.aligned.m8n8.x4.shared.b16 {%0,%1,%2,%3}, [%4];"
        : "=r"(r[0]), "=r"(r[1]), "=r"(r[2]), "=r"(r[3]) : "r"(addr));
}
__device__ __forceinline__ void ldsm4t(uint32_t* r, uint32_t addr) {
    asm volatile("ldmatrix.sync.aligned.m8n8.x4.trans.shared.b16 {%0,%1,%2,%3}, [%4];"
        : "=r"(r[0]), "=r"(r[1]), "=r"(r[2]), "=r"(r[3]) : "r"(addr));
}
__device__ __forceinline__ void ldsm2t(uint32_t* r, uint32_t addr) {
    asm volatile("ldmatrix.sync.aligned.m8n8.x2.trans.shared.b16 {%0,%1}, [%2];"
        : "=r"(r[0]), "=r"(r[1]) : "r"(addr));
}
__device__ __forceinline__ void mma_f16(float* d, const uint32_t* a, const uint32_t* b) {
    asm volatile("mma.sync.aligned.m16n8k16.row.col.f32.f16.f16.f32 "
        "{%0,%1,%2,%3}, {%4,%5,%6,%7}, {%8,%9}, {%0,%1,%2,%3};"
        : "+f"(d[0]), "+f"(d[1]), "+f"(d[2]), "+f"(d[3])
        : "r"(a[0]), "r"(a[1]), "r"(a[2]), "r"(a[3]), "r"(b[0]), "r"(b[1]));
}
__device__ __forceinline__ void split_h(float x, __half& h, __half& l) {
    h = __float2half_rn(x);
    l = __float2half_rn(x - __half2float(h));
}
__device__ __forceinline__ float sigf(float x) { return 1.f / (1.f + __expf(-x)); }

// ---------------- setup kernels ----------------
__global__ void k_dinv(const float* __restrict__ A) {
    int row = blockIdx.x;
    const float* ap = A + (size_t)row * NN;
    float s = 0.f;
    for (int i = threadIdx.x; i < NN; i += 128) s += ap[i];
    __shared__ float red[4];
    for (int o = 16; o; o >>= 1) s += __shfl_xor_sync(0xffffffffu, s, o);
    if ((threadIdx.x & 31) == 0) red[threadIdx.x >> 5] = s;
    __syncthreads();
    if (threadIdx.x == 0) {
        float d = red[0] + red[1] + red[2] + red[3];
        g_dinv[row] = d > 0.f ? rsqrtf(d) : 0.f;
    }
}

__global__ void k_an(const float* __restrict__ A) {
    int idx = blockIdx.x * 256 + threadIdx.x;
    int b = idx / (NN * NN);
    int r = (idx / NN) % NN;
    int m = idx % NN;
    float v = A[idx] * g_dinv[b * NN + r] * g_dinv[b * NN + m];
    g_An[idx] = __float2half_rn(v);
}

__global__ void k_es(const float* __restrict__ X, const float* __restrict__ Wse,
                     const float* __restrict__ bse, float* __restrict__ out) {
    int idx = blockIdx.x * 256 + threadIdx.x;
    int node = idx >> 7, j = idx & 127;
    const float* x0 = X + (size_t)node * TT * NIN;
    float acc = bse[j];
    #pragma unroll
    for (int q = 0; q < NIN; q++) acc += x0[q] * Wse[q * NE + j];
    g_es[idx] = acc;
    if (j < NIN) out[(size_t)node * TT * NIN + j] = x0[j];
}

__global__ void k_wz(const float* __restrict__ Wpe, const float* __restrict__ bpe,
    const float* __restrict__ Wii, const float* __restrict__ bii,
    const float* __restrict__ Whi, const float* __restrict__ bhi,
    const float* __restrict__ Wif, const float* __restrict__ bif,
    const float* __restrict__ Whf, const float* __restrict__ bhf,
    const float* __restrict__ Wig, const float* __restrict__ big,
    const float* __restrict__ Whg, const float* __restrict__ bhg,
    const float* __restrict__ Wio, const float* __restrict__ bio,
    const float* __restrict__ Who, const float* __restrict__ bho) {
    int idx = blockIdx.x * 256 + threadIdx.x;   // [k][n]
    int k = idx >> 9, n = idx & 511;
    int ch = n >> 2, g = n & 3;
    const float* Wg  = g == 0 ? Wii : g == 1 ? Wif : g == 2 ? Wig : Wio;
    const float* Whx = g == 0 ? Whi : g == 1 ? Whf : g == 2 ? Whg : Who;
    float v;
    if (k < 128) {
        v = 0.f;
        for (int p = 0; p < NE; p++) v += Wpe[k * NE + p] * Wg[(NE + p) * NH + ch];
    } else {
        v = Whx[(k - 128) * NH + ch];
    }
    g_Wz[idx] = __float2half_rn(v);
    if (k == 0) {
        const float* bg  = g == 0 ? bii : g == 1 ? bif : g == 2 ? big : bio;
        const float* bhx = g == 0 ? bhi : g == 1 ? bhf : g == 2 ? bhg : bho;
        float bv = bg[ch] + bhx[ch];
        for (int p = 0; p < NE; p++) bv += bpe[p] * Wg[(NE + p) * NH + ch];
        g_b0[n] = bv;
    }
}

__global__ void k_esw(const float* __restrict__ Wii, const float* __restrict__ Wif,
                      const float* __restrict__ Wig, const float* __restrict__ Wio) {
    int idx = blockIdx.x * 256 + threadIdx.x;
    int node = idx >> 9, j = idx & 511;
    int ch = j >> 2, g = j & 3;
    const float* Wg = g == 0 ? Wii : g == 1 ? Wif : g == 2 ? Wig : Wio;
    const float* e = g_es + (size_t)node * NE;
    float acc = g_b0[j];
    for (int p = 0; p < NE; p++) acc += e[p] * Wg[p * NH + ch];
    g_esW[idx] = acc;
}

__global__ void k_wo(const float* __restrict__ Wout) {
    int idx = blockIdx.x * 256 + threadIdx.x;   // NH*NIN, [k][n]
    split_h(Wout[idx], g_Wo_hi[idx], g_Wo_lo[idx]);
}

__global__ void k_zero() {
    int idx = blockIdx.x * 256 + threadIdx.x;
    g_h[0][idx] = __float2half(0.f);
    if (idx == 0) { g_barc = 0; g_barg = 0; }
}

// ---------------- smem layout (bytes) ----------------
#define S_AN      0u          // [32][520] fp16 = 33280 (resident all steps)
#define S_HH_HI   33280u      // [32][264] fp16
#define S_HH_LO   50176u      // [32][264] fp16 (cols 0-127 used, phase C)
#define S_W       67072u      // 2 x [64][264] fp16 (phase B dbl-buf; phase C Wo hi/lo [128][72])
#define WB(s)     (S_W + (s) * 33792u)
#define S_HC      134656u     // phase A h chunk [128][136] fp16 = 34816; phase B zb [32][260] f32
#define S_HN      169472u     // [32][132] f32 (resident)
#define S_SC      186368u     // [32][132] f32 (resident c state)
#define SMEM_TOT  203264

// ---------------- persistent all-steps kernel ----------------
// grid 128 (node tiles of 32, all co-resident), block 512 (16 warps)
__global__ __launch_bounds__(512, 1) void k_steps(const float* __restrict__ bout,
                                                  float* __restrict__ out) {
    extern __shared__ char sm[];
    uint32_t smb = smem_u32(sm);
    int tid = threadIdx.x, lane = tid & 31, w = tid >> 5;
    long node0 = (long)blockIdx.x * 32;
    int b = (int)(node0 >> 9);

    int a_r = (lane & 7) + ((lane >> 3) & 1) * 8;
    int a_c = ((lane >> 4) & 1) * 8;
    int bt_r = lane & 15;
    int bt_c = ((lane >> 4) & 1) * 8;
    int wm = w >> 3, wn = w & 7;

    float* zb = (float*)(sm + S_HC);
    float* hn = (float*)(sm + S_HN);
    float* sc = (float*)(sm + S_SC);

    // ---- one-time init: An resident, sc/hn zero, bout regs ----
    #pragma unroll
    for (int i = 0; i < 4; i++) {
        int idx = i * 512 + tid;
        int row = idx >> 6, seg = idx & 63;
        *(uint4*)(sm + S_AN + (row * 520 + seg * 8) * 2) =
            *((const uint4*)(g_An + (node0 + row) * (long)NN) + seg);
    }
    for (int i = tid; i < 32 * 132; i += 512) { sc[i] = 0.f; hn[i] = 0.f; }
    int pcol = wn * 8 + (lane & 3) * 2;
    float b0v = bout[pcol], b1v = bout[pcol + 1];
    __syncthreads();

    for (int t = 1; t < TT; t++) {
        int pp = (t + 1) & 1, pn = t & 1;
        const __half* hp = g_h[pp];

        // ---- own h (from resident hn) -> HH cols 128-255 ----
        {
            int row = tid >> 4, seg = tid & 15;
            const float* hr = hn + row * 132 + seg * 8;
            __half hh[8];
            #pragma unroll
            for (int j = 0; j < 8; j++) hh[j] = __float2half_rn(hr[j]);
            *(uint4*)(sm + S_HH_HI + (row * 264 + 128 + seg * 8) * 2) = *(const uint4*)hh;
        }

        // ---- Phase A: H = An(resident) @ h (4 K-chunks of 128) ----
        float accA[2][4];
        #pragma unroll
        for (int nt = 0; nt < 2; nt++)
            #pragma unroll
            for (int q = 0; q < 4; q++) accA[nt][q] = 0.f;

        {   // chunk 0 (L2-coherent loads: no per-launch L1 flush anymore)
            #pragma unroll
            for (int i = 0; i < 4; i++) {
                int idx = i * 512 + tid;
                int hr = idx >> 4, hs = idx & 15;
                uint4 v = __ldcg((const uint4*)(hp + ((long)b * NN + hr) * NH) + hs);
                *(uint4*)(sm + S_HC + (hr * 136 + hs * 8) * 2) = v;
            }
        }
        __syncthreads();

        for (int c = 0; c < 4; c++) {
            uint4 sh[4];
            if (c < 3) {
                #pragma unroll
                for (int i = 0; i < 4; i++) {
                    int idx = i * 512 + tid;
                    int hr = idx >> 4, hs = idx & 15;
                    sh[i] = __ldcg((const uint4*)(hp + ((long)b * NN + (c + 1) * 128 + hr) * NH) + hs);
                }
            }
            #pragma unroll
            for (int kk = 0; kk < 8; kk++) {
                uint32_t aH[4], b0[4];
                uint32_t aoff = (uint32_t)(((wm * 16 + a_r) * 520 + c * 128 + kk * 16 + a_c) * 2);
                ldsm4(aH, smb + S_AN + aoff);
                uint32_t boff = (uint32_t)(((kk * 16 + bt_r) * 136 + wn * 16 + bt_c) * 2);
                ldsm4t(b0, smb + S_HC + boff);
                mma_f16(accA[0], aH, b0);
                mma_f16(accA[1], aH, b0 + 2);
            }
            __syncthreads();
            if (c < 3) {
                #pragma unroll
                for (int i = 0; i < 4; i++) {
                    int idx = i * 512 + tid;
                    int hr = idx >> 4, hs = idx & 15;
                    *(uint4*)(sm + S_HC + (hr * 136 + hs * 8) * 2) = sh[i];
                }
                __syncthreads();
            }
        }

        // ---- HH epilogue: H -> HH_HI cols 0-127 ----
        {
            int r0 = wm * 16 + (lane >> 2), r1 = r0 + 8;
            #pragma unroll
            for (int nt = 0; nt < 2; nt++) {
                int col = wn * 16 + nt * 8 + (lane & 3) * 2;
                __half2 ph;
                ph.x = __float2half_rn(accA[nt][0]);
                ph.y = __float2half_rn(accA[nt][1]);
                *(__half2*)(sm + S_HH_HI + (r0 * 264 + col) * 2) = ph;
                ph.x = __float2half_rn(accA[nt][2]);
                ph.y = __float2half_rn(accA[nt][3]);
                *(__half2*)(sm + S_HH_HI + (r1 * 264 + col) * 2) = ph;
            }
        }

        // ---- Phase B: z = esW + [H|h] @ Wz (8 W tiles, dbl-buffered) ----
        float accB[4][4];
        #pragma unroll
        for (int nt = 0; nt < 4; nt++)
            #pragma unroll
            for (int q = 0; q < 4; q++) accB[nt][q] = 0.f;

        {
            #pragma unroll
            for (int i = 0; i < 4; i++) {
                int idx = i * 512 + tid;
                int row = idx >> 5, seg = idx & 31;
                *(uint4*)(sm + WB(0) + (row * 264 + seg * 8) * 2) =
                    *(const uint4*)(g_Wz + (long)row * NZ + seg * 8);
            }
        }
        __syncthreads();

        for (int wt = 0; wt < 8; wt++) {
            int nc = wt >> 2, kc = wt & 3;
            uint4 stg[4];
            if (wt < 7) {
                int n2 = (wt + 1) >> 2, k2 = (wt + 1) & 3;
                #pragma unroll
                for (int i = 0; i < 4; i++) {
                    int idx = i * 512 + tid;
                    int row = idx >> 5, seg = idx & 31;
                    stg[i] = *(const uint4*)(g_Wz + (long)(k2 * 64 + row) * NZ + n2 * 256 + seg * 8);
                }
            }
            uint32_t wbuf = smb + WB(wt & 1);
            #pragma unroll
            for (int kk = 0; kk < 4; kk++) {
                uint32_t aH[4];
                uint32_t aoff = (uint32_t)(((wm * 16 + a_r) * 264 + kc * 64 + kk * 16 + a_c) * 2);
                ldsm4(aH, smb + S_HH_HI + aoff);
                uint32_t bf[2][4];
                #pragma unroll
                for (int p = 0; p < 2; p++) {
                    uint32_t boff = (uint32_t)(((kk * 16 + bt_r) * 264 + wn * 32 + p * 16 + bt_c) * 2);
                    ldsm4t(bf[p], wbuf + boff);
                }
                mma_f16(accB[0], aH, bf[0]);
                mma_f16(accB[1], aH, bf[0] + 2);
                mma_f16(accB[2], aH, bf[1]);
                mma_f16(accB[3], aH, bf[1] + 2);
            }
            if (wt < 7) {
                uint32_t wb2 = WB((wt + 1) & 1);
                #pragma unroll
                for (int i = 0; i < 4; i++) {
                    int idx = i * 512 + tid;
                    int row = idx >> 5, seg = idx & 31;
                    *(uint4*)(sm + wb2 + (row * 264 + seg * 8) * 2) = stg[i];
                }
            }
            __syncthreads();

            if (kc == 3) {
                {
                    int r0 = wm * 16 + (lane >> 2), r1 = r0 + 8;
                    #pragma unroll
                    for (int nt = 0; nt < 4; nt++) {
                        int col = wn * 32 + nt * 8 + (lane & 3) * 2;
                        zb[r0 * 260 + col]     = accB[nt][0];
                        zb[r0 * 260 + col + 1] = accB[nt][1];
                        zb[r1 * 260 + col]     = accB[nt][2];
                        zb[r1 * 260 + col + 1] = accB[nt][3];
                        #pragma unroll
                        for (int q = 0; q < 4; q++) accB[nt][q] = 0.f;
                    }
                }
                __syncthreads();
                {
                    int row = tid >> 4, g16 = tid & 15;
                    long node = node0 + row;
                    #pragma unroll
                    for (int q = 0; q < 4; q++) {
                        int ch = nc * 64 + q * 16 + g16;
                        int colz = q * 64 + g16 * 4;
                        float4 z4 = *(const float4*)(zb + row * 260 + colz);
                        float4 e4 = *(const float4*)(g_esW + node * NZ + nc * 256 + colz);
                        float it = sigf(z4.x + e4.x);
                        float ft = sigf(z4.y + e4.y);
                        float gt = tanhf(z4.z + e4.z);
                        float ot = sigf(z4.w + e4.w);
                        float cn = ft * sc[row * 132 + ch] + it * gt;
                        float hv = ot * tanhf(cn);
                        sc[row * 132 + ch] = cn;
                        hn[row * 132 + ch] = hv;
                    }
                }
                __syncthreads();
            }
        }

        // ---- writeback h(fp16, L2); stage hn split + Wo tiles ----
        {
            __half* hw = g_h[pn];
            #pragma unroll
            for (int i = 0; i < 2; i++) {
                int idx = i * 512 + tid;
                int row = idx >> 5, c4 = (idx & 31) * 4;
                long base = (node0 + row) * NH + c4;
                float4 hv4 = *(const float4*)(hn + row * 132 + c4);
                __half hh[4];
                hh[0] = __float2half_rn(hv4.x); hh[1] = __float2half_rn(hv4.y);
                hh[2] = __float2half_rn(hv4.z); hh[3] = __float2half_rn(hv4.w);
                __stcg((uint2*)(hw + base), *(const uint2*)hh);
            }
            #pragma unroll
            for (int i = 0; i < 4; i++) {
                int idx = i * 512 + tid;
                int row = idx >> 6, c2 = (idx & 63) * 2;
                float hv0 = hn[row * 132 + c2], hv1 = hn[row * 132 + c2 + 1];
                __half h0, l0, h1, l1;
                split_h(hv0, h0, l0); split_h(hv1, h1, l1);
                __half2 ph; ph.x = h0; ph.y = h1;
                __half2 pl; pl.x = l0; pl.y = l1;
                *(__half2*)(sm + S_HH_HI + (row * 264 + c2) * 2) = ph;
                *(__half2*)(sm + S_HH_LO + (row * 264 + c2) * 2) = pl;
            }
            #pragma unroll
            for (int i = 0; i < 2; i++) {
                int idx = i * 512 + tid;
                int row = idx >> 3, seg = idx & 7;
                *(uint4*)(sm + WB(0) + (row * 72 + seg * 8) * 2) =
                    *((const uint4*)(g_Wo_hi + row * NIN) + seg);
                *(uint4*)(sm + WB(1) + (row * 72 + seg * 8) * 2) =
                    *((const uint4*)(g_Wo_lo + row * NIN) + seg);
            }
        }
        __syncthreads();

        // ---- Phase C: out[t] = out[t-1] + hn @ Wout + bout (3-term split MMA) ----
        {
            float accC[4] = {0.f, 0.f, 0.f, 0.f};
            #pragma unroll
            for (int kk = 0; kk < 8; kk++) {
                uint32_t aH[4], aL[4], bH[2], bL[2];
                uint32_t aoff = (uint32_t)(((wm * 16 + a_r) * 264 + kk * 16 + a_c) * 2);
                ldsm4(aH, smb + S_HH_HI + aoff);
                ldsm4(aL, smb + S_HH_LO + aoff);
                uint32_t boff = (uint32_t)(((kk * 16 + bt_r) * 72 + wn * 8) * 2);
                ldsm2t(bH, smb + WB(0) + boff);
                ldsm2t(bL, smb + WB(1) + boff);
                mma_f16(accC, aH, bH);
                mma_f16(accC, aH, bL);
                mma_f16(accC, aL, bH);
            }
            int r0 = wm * 16 + (lane >> 2), r1 = r0 + 8;
            long pb0 = (((node0 + r0) * TT) + (t - 1)) * NIN + pcol;
            long ob0 = (((node0 + r0) * TT) + t) * NIN + pcol;
            long pb1 = (((node0 + r1) * TT) + (t - 1)) * NIN + pcol;
            long ob1 = (((node0 + r1) * TT) + t) * NIN + pcol;
            float2 p0 = *(const float2*)(out + pb0);
            float2 p1 = *(const float2*)(out + pb1);
            float2 w0 = make_float2(p0.x + accC[0] + b0v, p0.y + accC[1] + b1v);
            float2 w1 = make_float2(p1.x + accC[2] + b0v, p1.y + accC[3] + b1v);
            *(float2*)(out + ob0) = w0;
            *(float2*)(out + ob1) = w1;
        }

        // ---- grid-wide barrier (h visibility for next step) ----
        if (t < TT - 1) {
            __threadfence();
            __syncthreads();
            if (tid == 0) {
                int v = atomicAdd(&g_barc, 1);
                if (v == 128 * t - 1) {
                    atomicExch(&g_barg, t);
                } else {
                    while (*((volatile int*)&g_barg) < t) { }
                }
            }
            __syncthreads();
        }
    }
}

// ---------------- launch ----------------
extern "C" void kernel_launch(void* const* d_in, const int* in_sizes, int n_in,
                              void* d_out, int out_size) {
    (void)in_sizes; (void)n_in; (void)out_size;
    const float* X    = (const float*)d_in[0];
    const float* A    = (const float*)d_in[1];
    const float* Wse  = (const float*)d_in[2];
    const float* bse  = (const float*)d_in[3];
    const float* Wpe  = (const float*)d_in[4];
    const float* bpe  = (const float*)d_in[5];
    const float* Wii  = (const float*)d_in[6];
    const float* bii  = (const float*)d_in[7];
    const float* Whi  = (const float*)d_in[8];
    const float* bhi  = (const float*)d_in[9];
    const float* Wif  = (const float*)d_in[10];
    const float* bif  = (const float*)d_in[11];
    const float* Whf  = (const float*)d_in[12];
    const float* bhf  = (const float*)d_in[13];
    const float* Wig  = (const float*)d_in[14];
    const float* big  = (const float*)d_in[15];
    const float* Whg  = (const float*)d_in[16];
    const float* bhg  = (const float*)d_in[17];
    const float* Wio  = (const float*)d_in[18];
    const float* bio  = (const float*)d_in[19];
    const float* Who  = (const float*)d_in[20];
    const float* bho  = (const float*)d_in[21];
    const float* Wout = (const float*)d_in[22];
    const float* bout = (const float*)d_in[23];
    float* out = (float*)d_out;

    cudaFuncSetAttribute(k_steps, cudaFuncAttributeMaxDynamicSharedMemorySize, SMEM_TOT);

    k_dinv<<<BB * NN, 128>>>(A);
    k_an<<<(BB * NN * NN) / 256, 256>>>(A);
    k_es<<<(NODES * NE) / 256, 256>>>(X, Wse, bse, out);
    k_wz<<<(256 * NZ) / 256, 256>>>(Wpe, bpe, Wii, bii, Whi, bhi, Wif, bif,
                                    Whf, bhf, Wig, big, Whg, bhg,
                                    Wio, bio, Who, bho);
    k_esw<<<(NODES * NZ) / 256, 256>>>(Wii, Wif, Wig, Wio);
    k_wo<<<(NH * NIN) / 256, 256>>>(Wout);
    k_zero<<<(NODES * NH) / 256, 256>>>();

    k_steps<<<128, 512, SMEM_TOT>>>(bout, out);
}

// round 14
// speedup vs baseline: 2.1918x; 1.0498x over previous
#include <cuda_runtime.h>
#include <cuda_fp16.h>
#include <math.h>
#include <stdint.h>

#define BB 8
#define NN 512
#define TT 64
#define NIN 64
#define NE 128
#define NH 128
#define NZ 512
#define NODES (BB*NN)   // 4096

// ---------------- persistent device scratch ----------------
__device__ float g_dinv[BB*NN];
__device__ __half g_An[BB*NN*NN];        // fp16 single
__device__ __half g_h[2][NODES*NH];      // fp16 single, ping-pong
__device__ float g_es[NODES*NE];
__device__ float g_esW[NODES*NZ];
__device__ float g_b0[NZ];
__device__ __half g_Wz[256*NZ];          // [k][n], fp16 single
__device__ __half g_Wo_hi[NH*NIN], g_Wo_lo[NH*NIN];   // [k][n] split fp16
__device__ int g_barc;
__device__ int g_barg;

// ---------------- helpers ----------------
__device__ __forceinline__ uint32_t smem_u32(const void* p) {
    uint32_t a;
    asm("{ .reg .u64 t; cvta.to.shared.u64 t, %1; cvt.u32.u64 %0, t; }" : "=r"(a) : "l"(p));
    return a;
}
__device__ __forceinline__ void ldsm4(uint32_t* r, uint32_t addr) {
    asm volatile("ldmatrix.sync.aligned.m8n8.x4.shared.b16 {%0,%1,%2,%3}, [%4];"
        : "=r"(r[0]), "=r"(r[1]), "=r"(r[2]), "=r"(r[3]) : "r"(addr));
}
__device__ __forceinline__ void ldsm4t(uint32_t* r, uint32_t addr) {
    asm volatile("ldmatrix.sync.aligned.m8n8.x4.trans.shared.b16 {%0,%1,%2,%3}, [%4];"
        : "=r"(r[0]), "=r"(r[1]), "=r"(r[2]), "=r"(r[3]) : "r"(addr));
}
__device__ __forceinline__ void ldsm2t(uint32_t* r, uint32_t addr) {
    asm volatile("ldmatrix.sync.aligned.m8n8.x2.trans.shared.b16 {%0,%1}, [%2];"
        : "=r"(r[0]), "=r"(r[1]) : "r"(addr));
}
__device__ __forceinline__ void mma_f16(float* d, const uint32_t* a, const uint32_t* b) {
    asm volatile("mma.sync.aligned.m16n8k16.row.col.f32.f16.f16.f32 "
        "{%0,%1,%2,%3}, {%4,%5,%6,%7}, {%8,%9}, {%0,%1,%2,%3};"
        : "+f"(d[0]), "+f"(d[1]), "+f"(d[2]), "+f"(d[3])
        : "r"(a[0]), "r"(a[1]), "r"(a[2]), "r"(a[3]), "r"(b[0]), "r"(b[1]));
}
__device__ __forceinline__ void split_h(float x, __half& h, __half& l) {
    h = __float2half_rn(x);
    l = __float2half_rn(x - __half2float(h));
}
__device__ __forceinline__ float sigf(float x) { return 1.f / (1.f + __expf(-x)); }

// ---------------- setup kernels ----------------
__global__ void k_dinv(const float* __restrict__ A) {
    int row = blockIdx.x;
    const float* ap = A + (size_t)row * NN;
    float s = 0.f;
    for (int i = threadIdx.x; i < NN; i += 128) s += ap[i];
    __shared__ float red[4];
    for (int o = 16; o; o >>= 1) s += __shfl_xor_sync(0xffffffffu, s, o);
    if ((threadIdx.x & 31) == 0) red[threadIdx.x >> 5] = s;
    __syncthreads();
    if (threadIdx.x == 0) {
        float d = red[0] + red[1] + red[2] + red[3];
        g_dinv[row] = d > 0.f ? rsqrtf(d) : 0.f;
    }
}

__global__ void k_an(const float* __restrict__ A) {
    int idx = blockIdx.x * 256 + threadIdx.x;
    int b = idx / (NN * NN);
    int r = (idx / NN) % NN;
    int m = idx % NN;
    float v = A[idx] * g_dinv[b * NN + r] * g_dinv[b * NN + m];
    g_An[idx] = __float2half_rn(v);
}

__global__ void k_es(const float* __restrict__ X, const float* __restrict__ Wse,
                     const float* __restrict__ bse, float* __restrict__ out) {
    int idx = blockIdx.x * 256 + threadIdx.x;
    int node = idx >> 7, j = idx & 127;
    const float* x0 = X + (size_t)node * TT * NIN;
    float acc = bse[j];
    #pragma unroll
    for (int q = 0; q < NIN; q++) acc += x0[q] * Wse[q * NE + j];
    g_es[idx] = acc;
    if (j < NIN) out[(size_t)node * TT * NIN + j] = x0[j];
}

__global__ void k_wz(const float* __restrict__ Wpe, const float* __restrict__ bpe,
    const float* __restrict__ Wii, const float* __restrict__ bii,
    const float* __restrict__ Whi, const float* __restrict__ bhi,
    const float* __restrict__ Wif, const float* __restrict__ bif,
    const float* __restrict__ Whf, const float* __restrict__ bhf,
    const float* __restrict__ Wig, const float* __restrict__ big,
    const float* __restrict__ Whg, const float* __restrict__ bhg,
    const float* __restrict__ Wio, const float* __restrict__ bio,
    const float* __restrict__ Who, const float* __restrict__ bho) {
    int idx = blockIdx.x * 256 + threadIdx.x;   // [k][n]
    int k = idx >> 9, n = idx & 511;
    int ch = n >> 2, g = n & 3;
    const float* Wg  = g == 0 ? Wii : g == 1 ? Wif : g == 2 ? Wig : Wio;
    const float* Whx = g == 0 ? Whi : g == 1 ? Whf : g == 2 ? Whg : Who;
    float v;
    if (k < 128) {
        v = 0.f;
        for (int p = 0; p < NE; p++) v += Wpe[k * NE + p] * Wg[(NE + p) * NH + ch];
    } else {
        v = Whx[(k - 128) * NH + ch];
    }
    g_Wz[idx] = __float2half_rn(v);
    if (k == 0) {
        const float* bg  = g == 0 ? bii : g == 1 ? bif : g == 2 ? big : bio;
        const float* bhx = g == 0 ? bhi : g == 1 ? bhf : g == 2 ? bhg : bho;
        float bv = bg[ch] + bhx[ch];
        for (int p = 0; p < NE; p++) bv += bpe[p] * Wg[(NE + p) * NH + ch];
        g_b0[n] = bv;
    }
}

__global__ void k_esw(const float* __restrict__ Wii, const float* __restrict__ Wif,
                      const float* __restrict__ Wig, const float* __restrict__ Wio) {
    int idx = blockIdx.x * 256 + threadIdx.x;
    int node = idx >> 9, j = idx & 511;
    int ch = j >> 2, g = j & 3;
    const float* Wg = g == 0 ? Wii : g == 1 ? Wif : g == 2 ? Wig : Wio;
    const float* e = g_es + (size_t)node * NE;
    float acc = g_b0[j];
    for (int p = 0; p < NE; p++) acc += e[p] * Wg[p * NH + ch];
    g_esW[idx] = acc;
}

__global__ void k_wo(const float* __restrict__ Wout) {
    int idx = blockIdx.x * 256 + threadIdx.x;   // NH*NIN, [k][n]
    split_h(Wout[idx], g_Wo_hi[idx], g_Wo_lo[idx]);
}

__global__ void k_zero() {
    int idx = blockIdx.x * 256 + threadIdx.x;
    g_h[0][idx] = __float2half(0.f);
    if (idx == 0) { g_barc = 0; g_barg = 0; }
}

// ---------------- smem layout (bytes) ----------------
#define S_AN      0u          // [32][520] fp16 (resident all steps)
#define S_HH_HI   33280u      // [32][264] fp16
#define S_HH_LO   50176u      // [32][264] fp16 (cols 0-127 used, phase C)
#define S_W       67072u      // 2 x [64][264] fp16 (phase B dbl-buf; phase C Wo hi/lo [128][72])
#define WB(s)     (S_W + (s) * 33792u)
#define S_HC      134656u     // phase A h chunk [128][136] fp16; phase B zb [32][260] f32
#define S_HN      169472u     // [32][132] f32 (resident)
#define S_SC      186368u     // [32][132] f32 (resident c state)
#define SMEM_TOT  203264

// ---------------- persistent all-steps kernel ----------------
// grid 128 (node tiles of 32, all co-resident), block 512 (16 warps)
__global__ __launch_bounds__(512, 1) void k_steps(const float* __restrict__ bout,
                                                  float* __restrict__ out) {
    extern __shared__ char sm[];
    uint32_t smb = smem_u32(sm);
    int tid = threadIdx.x, lane = tid & 31, w = tid >> 5;
    long node0 = (long)blockIdx.x * 32;
    int b = (int)(node0 >> 9);

    int a_r = (lane & 7) + ((lane >> 3) & 1) * 8;
    int a_c = ((lane >> 4) & 1) * 8;
    int bt_r = lane & 15;
    int bt_c = ((lane >> 4) & 1) * 8;
    int wm = w >> 3, wn = w & 7;

    float* zb = (float*)(sm + S_HC);
    float* hn = (float*)(sm + S_HN);
    float* sc = (float*)(sm + S_SC);

    // ---- one-time init: An resident, sc/hn zero, bout + running out in regs ----
    #pragma unroll
    for (int i = 0; i < 4; i++) {
        int idx = i * 512 + tid;
        int row = idx >> 6, seg = idx & 63;
        *(uint4*)(sm + S_AN + (row * 520 + seg * 8) * 2) =
            *((const uint4*)(g_An + (node0 + row) * (long)NN) + seg);
    }
    for (int i = tid; i < 32 * 132; i += 512) { sc[i] = 0.f; hn[i] = 0.f; }
    int pcol = wn * 8 + (lane & 3) * 2;
    float b0v = bout[pcol], b1v = bout[pcol + 1];
    int cr0 = wm * 16 + (lane >> 2), cr1 = cr0 + 8;
    float2 orun0 = *(const float2*)(out + ((node0 + cr0) * TT) * NIN + pcol);
    float2 orun1 = *(const float2*)(out + ((node0 + cr1) * TT) * NIN + pcol);
    __syncthreads();

    for (int t = 1; t < TT; t++) {
        int pp = (t + 1) & 1, pn = t & 1;
        const __half* hp = g_h[pp];
        bool last = (t == TT - 1);

        // ---- own h (from resident hn) -> HH cols 128-255 ----
        {
            int row = tid >> 4, seg = tid & 15;
            const float* hr = hn + row * 132 + seg * 8;
            __half hh[8];
            #pragma unroll
            for (int j = 0; j < 8; j++) hh[j] = __float2half_rn(hr[j]);
            *(uint4*)(sm + S_HH_HI + (row * 264 + 128 + seg * 8) * 2) = *(const uint4*)hh;
        }

        // ---- Phase A: H = An(resident) @ h (4 K-chunks of 128) ----
        float accA[2][4];
        #pragma unroll
        for (int nt = 0; nt < 2; nt++)
            #pragma unroll
            for (int q = 0; q < 4; q++) accA[nt][q] = 0.f;

        {
            #pragma unroll
            for (int i = 0; i < 4; i++) {
                int idx = i * 512 + tid;
                int hr = idx >> 4, hs = idx & 15;
                uint4 v = __ldcg((const uint4*)(hp + ((long)b * NN + hr) * NH) + hs);
                *(uint4*)(sm + S_HC + (hr * 136 + hs * 8) * 2) = v;
            }
        }
        __syncthreads();

        for (int c = 0; c < 4; c++) {
            uint4 sh[4];
            if (c < 3) {
                #pragma unroll
                for (int i = 0; i < 4; i++) {
                    int idx = i * 512 + tid;
                    int hr = idx >> 4, hs = idx & 15;
                    sh[i] = __ldcg((const uint4*)(hp + ((long)b * NN + (c + 1) * 128 + hr) * NH) + hs);
                }
            }
            #pragma unroll
            for (int kk = 0; kk < 8; kk++) {
                uint32_t aH[4], b0[4];
                uint32_t aoff = (uint32_t)(((wm * 16 + a_r) * 520 + c * 128 + kk * 16 + a_c) * 2);
                ldsm4(aH, smb + S_AN + aoff);
                uint32_t boff = (uint32_t)(((kk * 16 + bt_r) * 136 + wn * 16 + bt_c) * 2);
                ldsm4t(b0, smb + S_HC + boff);
                mma_f16(accA[0], aH, b0);
                mma_f16(accA[1], aH, b0 + 2);
            }
            __syncthreads();
            if (c < 3) {
                #pragma unroll
                for (int i = 0; i < 4; i++) {
                    int idx = i * 512 + tid;
                    int hr = idx >> 4, hs = idx & 15;
                    *(uint4*)(sm + S_HC + (hr * 136 + hs * 8) * 2) = sh[i];
                }
                __syncthreads();
            }
        }

        // ---- HH epilogue: H -> HH_HI cols 0-127 ----
        {
            int r0 = cr0, r1 = cr1;
            #pragma unroll
            for (int nt = 0; nt < 2; nt++) {
                int col = wn * 16 + nt * 8 + (lane & 3) * 2;
                __half2 ph;
                ph.x = __float2half_rn(accA[nt][0]);
                ph.y = __float2half_rn(accA[nt][1]);
                *(__half2*)(sm + S_HH_HI + (r0 * 264 + col) * 2) = ph;
                ph.x = __float2half_rn(accA[nt][2]);
                ph.y = __float2half_rn(accA[nt][3]);
                *(__half2*)(sm + S_HH_HI + (r1 * 264 + col) * 2) = ph;
            }
        }

        // ---- Phase B: z = esW + [H|h] @ Wz (8 W tiles, dbl-buffered) ----
        float accB[4][4];
        #pragma unroll
        for (int nt = 0; nt < 4; nt++)
            #pragma unroll
            for (int q = 0; q < 4; q++) accB[nt][q] = 0.f;

        {
            #pragma unroll
            for (int i = 0; i < 4; i++) {
                int idx = i * 512 + tid;
                int row = idx >> 5, seg = idx & 31;
                *(uint4*)(sm + WB(0) + (row * 264 + seg * 8) * 2) =
                    *(const uint4*)(g_Wz + (long)row * NZ + seg * 8);
            }
        }
        __syncthreads();

        for (int wt = 0; wt < 8; wt++) {
            int nc = wt >> 2, kc = wt & 3;
            uint4 stg[4];
            if (wt < 7) {
                int n2 = (wt + 1) >> 2, k2 = (wt + 1) & 3;
                #pragma unroll
                for (int i = 0; i < 4; i++) {
                    int idx = i * 512 + tid;
                    int row = idx >> 5, seg = idx & 31;
                    stg[i] = *(const uint4*)(g_Wz + (long)(k2 * 64 + row) * NZ + n2 * 256 + seg * 8);
                }
            }
            uint32_t wbuf = smb + WB(wt & 1);
            #pragma unroll
            for (int kk = 0; kk < 4; kk++) {
                uint32_t aH[4];
                uint32_t aoff = (uint32_t)(((wm * 16 + a_r) * 264 + kc * 64 + kk * 16 + a_c) * 2);
                ldsm4(aH, smb + S_HH_HI + aoff);
                uint32_t bf[2][4];
                #pragma unroll
                for (int p = 0; p < 2; p++) {
                    uint32_t boff = (uint32_t)(((kk * 16 + bt_r) * 264 + wn * 32 + p * 16 + bt_c) * 2);
                    ldsm4t(bf[p], wbuf + boff);
                }
                mma_f16(accB[0], aH, bf[0]);
                mma_f16(accB[1], aH, bf[0] + 2);
                mma_f16(accB[2], aH, bf[1]);
                mma_f16(accB[3], aH, bf[1] + 2);
            }
            if (wt < 7) {
                uint32_t wb2 = WB((wt + 1) & 1);
                #pragma unroll
                for (int i = 0; i < 4; i++) {
                    int idx = i * 512 + tid;
                    int row = idx >> 5, seg = idx & 31;
                    *(uint4*)(sm + wb2 + (row * 264 + seg * 8) * 2) = stg[i];
                }
            }
            __syncthreads();

            if (kc == 3) {
                // prefetch esW gate terms (independent of zb)
                float4 e4s[4];
                {
                    int row = tid >> 4, g16 = tid & 15;
                    long node = node0 + row;
                    #pragma unroll
                    for (int q = 0; q < 4; q++)
                        e4s[q] = *(const float4*)(g_esW + node * NZ + nc * 256 + q * 64 + g16 * 4);
                }
                {
                    int r0 = cr0, r1 = cr1;
                    #pragma unroll
                    for (int nt = 0; nt < 4; nt++) {
                        int col = wn * 32 + nt * 8 + (lane & 3) * 2;
                        zb[r0 * 260 + col]     = accB[nt][0];
                        zb[r0 * 260 + col + 1] = accB[nt][1];
                        zb[r1 * 260 + col]     = accB[nt][2];
                        zb[r1 * 260 + col + 1] = accB[nt][3];
                        #pragma unroll
                        for (int q = 0; q < 4; q++) accB[nt][q] = 0.f;
                    }
                }
                __syncthreads();
                {
                    int row = tid >> 4, g16 = tid & 15;
                    #pragma unroll
                    for (int q = 0; q < 4; q++) {
                        int ch = nc * 64 + q * 16 + g16;
                        int colz = q * 64 + g16 * 4;
                        float4 z4 = *(const float4*)(zb + row * 260 + colz);
                        float4 e4 = e4s[q];
                        float it = sigf(z4.x + e4.x);
                        float ft = sigf(z4.y + e4.y);
                        float gt = tanhf(z4.z + e4.z);
                        float ot = sigf(z4.w + e4.w);
                        float cn = ft * sc[row * 132 + ch] + it * gt;
                        float hv = ot * tanhf(cn);
                        sc[row * 132 + ch] = cn;
                        hn[row * 132 + ch] = hv;
                    }
                }
                __syncthreads();
            }
        }

        // ---- writeback h(fp16, L2); stage hn split + Wo tiles ----
        {
            __half* hw = g_h[pn];
            #pragma unroll
            for (int i = 0; i < 2; i++) {
                int idx = i * 512 + tid;
                int row = idx >> 5, c4 = (idx & 31) * 4;
                long base = (node0 + row) * NH + c4;
                float4 hv4 = *(const float4*)(hn + row * 132 + c4);
                __half hh[4];
                hh[0] = __float2half_rn(hv4.x); hh[1] = __float2half_rn(hv4.y);
                hh[2] = __float2half_rn(hv4.z); hh[3] = __float2half_rn(hv4.w);
                __stcg((uint2*)(hw + base), *(const uint2*)hh);
            }
            #pragma unroll
            for (int i = 0; i < 4; i++) {
                int idx = i * 512 + tid;
                int row = idx >> 6, c2 = (idx & 63) * 2;
                float hv0 = hn[row * 132 + c2], hv1 = hn[row * 132 + c2 + 1];
                __half h0, l0, h1, l1;
                split_h(hv0, h0, l0); split_h(hv1, h1, l1);
                __half2 ph; ph.x = h0; ph.y = h1;
                __half2 pl; pl.x = l0; pl.y = l1;
                *(__half2*)(sm + S_HH_HI + (row * 264 + c2) * 2) = ph;
                *(__half2*)(sm + S_HH_LO + (row * 264 + c2) * 2) = pl;
            }
            #pragma unroll
            for (int i = 0; i < 2; i++) {
                int idx = i * 512 + tid;
                int row = idx >> 3, seg = idx & 7;
                *(uint4*)(sm + WB(0) + (row * 72 + seg * 8) * 2) =
                    *((const uint4*)(g_Wo_hi + row * NIN) + seg);
                *(uint4*)(sm + WB(1) + (row * 72 + seg * 8) * 2) =
                    *((const uint4*)(g_Wo_lo + row * NIN) + seg);
            }
        }
        __threadfence();
        __syncthreads();

        // ---- EARLY barrier arrive (h published); wait is deferred past phase C ----
        if (!last && tid == 0) {
            int v = atomicAdd(&g_barc, 1);
            if (v == 128 * t - 1) atomicExch(&g_barg, t);
        }

        // ---- Phase C: out[t] = out[t-1](regs) + hn @ Wout + bout ----
        {
            float accC[4] = {0.f, 0.f, 0.f, 0.f};
            #pragma unroll
            for (int kk = 0; kk < 8; kk++) {
                uint32_t aH[4], aL[4], bH[2], bL[2];
                uint32_t aoff = (uint32_t)(((wm * 16 + a_r) * 264 + kk * 16 + a_c) * 2);
                ldsm4(aH, smb + S_HH_HI + aoff);
                ldsm4(aL, smb + S_HH_LO + aoff);
                uint32_t boff = (uint32_t)(((kk * 16 + bt_r) * 72 + wn * 8) * 2);
                ldsm2t(bH, smb + WB(0) + boff);
                ldsm2t(bL, smb + WB(1) + boff);
                mma_f16(accC, aH, bH);
                mma_f16(accC, aH, bL);
                mma_f16(accC, aL, bH);
            }
            orun0.x = (orun0.x + accC[0]) + b0v;
            orun0.y = (orun0.y + accC[1]) + b1v;
            orun1.x = (orun1.x + accC[2]) + b0v;
            orun1.y = (orun1.y + accC[3]) + b1v;
            long ob0 = (((node0 + cr0) * TT) + t) * NIN + pcol;
            long ob1 = (((node0 + cr1) * TT) + t) * NIN + pcol;
            *(float2*)(out + ob0) = orun0;
            *(float2*)(out + ob1) = orun1;
        }

        // ---- barrier wait (overlapped with phase C above) ----
        if (!last) {
            if (tid == 0) {
                while (*((volatile int*)&g_barg) < t) { }
            }
            __syncthreads();
        }
    }
}

// ---------------- launch ----------------
extern "C" void kernel_launch(void* const* d_in, const int* in_sizes, int n_in,
                              void* d_out, int out_size) {
    (void)in_sizes; (void)n_in; (void)out_size;
    const float* X    = (const float*)d_in[0];
    const float* A    = (const float*)d_in[1];
    const float* Wse  = (const float*)d_in[2];
    const float* bse  = (const float*)d_in[3];
    const float* Wpe  = (const float*)d_in[4];
    const float* bpe  = (const float*)d_in[5];
    const float* Wii  = (const float*)d_in[6];
    const float* bii  = (const float*)d_in[7];
    const float* Whi  = (const float*)d_in[8];
    const float* bhi  = (const float*)d_in[9];
    const float* Wif  = (const float*)d_in[10];
    const float* bif  = (const float*)d_in[11];
    const float* Whf  = (const float*)d_in[12];
    const float* bhf  = (const float*)d_in[13];
    const float* Wig  = (const float*)d_in[14];
    const float* big  = (const float*)d_in[15];
    const float* Whg  = (const float*)d_in[16];
    const float* bhg  = (const float*)d_in[17];
    const float* Wio  = (const float*)d_in[18];
    const float* bio  = (const float*)d_in[19];
    const float* Who  = (const float*)d_in[20];
    const float* bho  = (const float*)d_in[21];
    const float* Wout = (const float*)d_in[22];
    const float* bout = (const float*)d_in[23];
    float* out = (float*)d_out;

    cudaFuncSetAttribute(k_steps, cudaFuncAttributeMaxDynamicSharedMemorySize, SMEM_TOT);

    k_dinv<<<BB * NN, 128>>>(A);
    k_an<<<(BB * NN * NN) / 256, 256>>>(A);
    k_es<<<(NODES * NE) / 256, 256>>>(X, Wse, bse, out);
    k_wz<<<(256 * NZ) / 256, 256>>>(Wpe, bpe, Wii, bii, Whi, bhi, Wif, bif,
                                    Whf, bhf, Wig, big, Whg, bhg,
                                    Wio, bio, Who, bho);
    k_esw<<<(NODES * NZ) / 256, 256>>>(Wii, Wif, Wig, Wio);
    k_wo<<<(NH * NIN) / 256, 256>>>(Wout);
    k_zero<<<(NODES * NH) / 256, 256>>>();

    k_steps<<<128, 512, SMEM_TOT>>>(bout, out);
}

// round 15
// speedup vs baseline: 2.2085x; 1.0076x over previous
#include <cuda_runtime.h>
#include <cuda_fp16.h>
#include <math.h>
#include <stdint.h>

#define BB 8
#define NN 512
#define TT 64
#define NIN 64
#define NE 128
#define NH 128
#define NZ 512
#define NODES (BB*NN)   // 4096

// ---------------- persistent device scratch ----------------
__device__ float g_dinv[BB*NN];
__device__ __half g_An[BB*NN*NN];        // fp16 single
__device__ __half g_h[2][NODES*NH];      // fp16 single, ping-pong
__device__ float g_es[NODES*NE];
__device__ float g_esW[NODES*NZ];
__device__ float g_b0[NZ];
__device__ __half g_Wz[256*NZ];          // [k][n], fp16 single
__device__ __half g_Wo_hi[NH*NIN], g_Wo_lo[NH*NIN];   // [k][n] split fp16
__device__ int g_barc[BB];
__device__ int g_barg[BB];

// ---------------- helpers ----------------
__device__ __forceinline__ uint32_t smem_u32(const void* p) {
    uint32_t a;
    asm("{ .reg .u64 t; cvta.to.shared.u64 t, %1; cvt.u32.u64 %0, t; }" : "=r"(a) : "l"(p));
    return a;
}
__device__ __forceinline__ void ldsm4(uint32_t* r, uint32_t addr) {
    asm volatile("ldmatrix.sync.aligned.m8n8.x4.shared.b16 {%0,%1,%2,%3}, [%4];"
        : "=r"(r[0]), "=r"(r[1]), "=r"(r[2]), "=r"(r[3]) : "r"(addr));
}
__device__ __forceinline__ void ldsm4t(uint32_t* r, uint32_t addr) {
    asm volatile("ldmatrix.sync.aligned.m8n8.x4.trans.shared.b16 {%0,%1,%2,%3}, [%4];"
        : "=r"(r[0]), "=r"(r[1]), "=r"(r[2]), "=r"(r[3]) : "r"(addr));
}
__device__ __forceinline__ void ldsm2t(uint32_t* r, uint32_t addr) {
    asm volatile("ldmatrix.sync.aligned.m8n8.x2.trans.shared.b16 {%0,%1}, [%2];"
        : "=r"(r[0]), "=r"(r[1]) : "r"(addr));
}
__device__ __forceinline__ void mma_f16(float* d, const uint32_t* a, const uint32_t* b) {
    asm volatile("mma.sync.aligned.m16n8k16.row.col.f32.f16.f16.f32 "
        "{%0,%1,%2,%3}, {%4,%5,%6,%7}, {%8,%9}, {%0,%1,%2,%3};"
        : "+f"(d[0]), "+f"(d[1]), "+f"(d[2]), "+f"(d[3])
        : "r"(a[0]), "r"(a[1]), "r"(a[2]), "r"(a[3]), "r"(b[0]), "r"(b[1]));
}
__device__ __forceinline__ void split_h(float x, __half& h, __half& l) {
    h = __float2half_rn(x);
    l = __float2half_rn(x - __half2float(h));
}
__device__ __forceinline__ float sigf(float x) { return 1.f / (1.f + __expf(-x)); }

// ---------------- setup kernels ----------------
__global__ void k_dinv(const float* __restrict__ A) {
    int row = blockIdx.x;
    const float* ap = A + (size_t)row * NN;
    float s = 0.f;
    for (int i = threadIdx.x; i < NN; i += 128) s += ap[i];
    __shared__ float red[4];
    for (int o = 16; o; o >>= 1) s += __shfl_xor_sync(0xffffffffu, s, o);
    if ((threadIdx.x & 31) == 0) red[threadIdx.x >> 5] = s;
    __syncthreads();
    if (threadIdx.x == 0) {
        float d = red[0] + red[1] + red[2] + red[3];
        g_dinv[row] = d > 0.f ? rsqrtf(d) : 0.f;
    }
}

__global__ void k_an(const float* __restrict__ A) {
    int idx = blockIdx.x * 256 + threadIdx.x;
    int b = idx / (NN * NN);
    int r = (idx / NN) % NN;
    int m = idx % NN;
    float v = A[idx] * g_dinv[b * NN + r] * g_dinv[b * NN + m];
    g_An[idx] = __float2half_rn(v);
}

__global__ void k_es(const float* __restrict__ X, const float* __restrict__ Wse,
                     const float* __restrict__ bse, float* __restrict__ out) {
    int idx = blockIdx.x * 256 + threadIdx.x;
    int node = idx >> 7, j = idx & 127;
    const float* x0 = X + (size_t)node * TT * NIN;
    float acc = bse[j];
    #pragma unroll
    for (int q = 0; q < NIN; q++) acc += x0[q] * Wse[q * NE + j];
    g_es[idx] = acc;
    if (j < NIN) out[(size_t)node * TT * NIN + j] = x0[j];
}

__global__ void k_wz(const float* __restrict__ Wpe, const float* __restrict__ bpe,
    const float* __restrict__ Wii, const float* __restrict__ bii,
    const float* __restrict__ Whi, const float* __restrict__ bhi,
    const float* __restrict__ Wif, const float* __restrict__ bif,
    const float* __restrict__ Whf, const float* __restrict__ bhf,
    const float* __restrict__ Wig, const float* __restrict__ big,
    const float* __restrict__ Whg, const float* __restrict__ bhg,
    const float* __restrict__ Wio, const float* __restrict__ bio,
    const float* __restrict__ Who, const float* __restrict__ bho) {
    int idx = blockIdx.x * 256 + threadIdx.x;   // [k][n]
    int k = idx >> 9, n = idx & 511;
    int ch = n >> 2, g = n & 3;
    const float* Wg  = g == 0 ? Wii : g == 1 ? Wif : g == 2 ? Wig : Wio;
    const float* Whx = g == 0 ? Whi : g == 1 ? Whf : g == 2 ? Whg : Who;
    float v;
    if (k < 128) {
        v = 0.f;
        for (int p = 0; p < NE; p++) v += Wpe[k * NE + p] * Wg[(NE + p) * NH + ch];
    } else {
        v = Whx[(k - 128) * NH + ch];
    }
    g_Wz[idx] = __float2half_rn(v);
    if (k == 0) {
        const float* bg  = g == 0 ? bii : g == 1 ? bif : g == 2 ? big : bio;
        const float* bhx = g == 0 ? bhi : g == 1 ? bhf : g == 2 ? bhg : bho;
        float bv = bg[ch] + bhx[ch];
        for (int p = 0; p < NE; p++) bv += bpe[p] * Wg[(NE + p) * NH + ch];
        g_b0[n] = bv;
    }
}

__global__ void k_esw(const float* __restrict__ Wii, const float* __restrict__ Wif,
                      const float* __restrict__ Wig, const float* __restrict__ Wio) {
    int idx = blockIdx.x * 256 + threadIdx.x;
    int node = idx >> 9, j = idx & 511;
    int ch = j >> 2, g = j & 3;
    const float* Wg = g == 0 ? Wii : g == 1 ? Wif : g == 2 ? Wig : Wio;
    const float* e = g_es + (size_t)node * NE;
    float acc = g_b0[j];
    for (int p = 0; p < NE; p++) acc += e[p] * Wg[p * NH + ch];
    g_esW[idx] = acc;
}

__global__ void k_wo(const float* __restrict__ Wout) {
    int idx = blockIdx.x * 256 + threadIdx.x;   // NH*NIN, [k][n]
    split_h(Wout[idx], g_Wo_hi[idx], g_Wo_lo[idx]);
}

__global__ void k_zero() {
    int idx = blockIdx.x * 256 + threadIdx.x;
    g_h[0][idx] = __float2half(0.f);
    if (idx < BB) { g_barc[idx] = 0; g_barg[idx] = 0; }
}

// ---------------- smem layout (bytes) ----------------
#define S_AN      0u          // [32][520] fp16 (resident all steps)
#define S_HH_HI   33280u      // [32][264] fp16
#define S_HH_LO   50176u      // [32][264] fp16 (cols 0-127 used, phase C)
#define S_W       67072u      // 2 x [64][264] fp16 (phase B dbl-buf; phase C Wo hi/lo [128][72])
#define WB(s)     (S_W + (s) * 33792u)
#define S_HC      134656u     // phase A h chunk [128][136] fp16; phase B zb [32][260] f32
#define S_HN      169472u     // [32][132] f32 (resident)
#define S_SC      186368u     // [32][132] f32 (resident c state)
#define SMEM_TOT  203264

// ---------------- persistent all-steps kernel ----------------
// grid 128 (node tiles of 32, all co-resident; 16 CTAs per batch), block 512
__global__ __launch_bounds__(512, 1) void k_steps(const float* __restrict__ bout,
                                                  float* __restrict__ out) {
    extern __shared__ char sm[];
    uint32_t smb = smem_u32(sm);
    int tid = threadIdx.x, lane = tid & 31, w = tid >> 5;
    long node0 = (long)blockIdx.x * 32;
    int b = (int)(node0 >> 9);

    int a_r = (lane & 7) + ((lane >> 3) & 1) * 8;
    int a_c = ((lane >> 4) & 1) * 8;
    int bt_r = lane & 15;
    int bt_c = ((lane >> 4) & 1) * 8;
    int wm = w >> 3, wn = w & 7;

    float* zb = (float*)(sm + S_HC);
    float* hn = (float*)(sm + S_HN);
    float* sc = (float*)(sm + S_SC);

    // ---- one-time init: An resident, sc/hn zero, bout + running out in regs ----
    #pragma unroll
    for (int i = 0; i < 4; i++) {
        int idx = i * 512 + tid;
        int row = idx >> 6, seg = idx & 63;
        *(uint4*)(sm + S_AN + (row * 520 + seg * 8) * 2) =
            *((const uint4*)(g_An + (node0 + row) * (long)NN) + seg);
    }
    for (int i = tid; i < 32 * 132; i += 512) { sc[i] = 0.f; hn[i] = 0.f; }
    int pcol = wn * 8 + (lane & 3) * 2;
    float b0v = bout[pcol], b1v = bout[pcol + 1];
    int cr0 = wm * 16 + (lane >> 2), cr1 = cr0 + 8;
    float2 orun0 = *(const float2*)(out + ((node0 + cr0) * TT) * NIN + pcol);
    float2 orun1 = *(const float2*)(out + ((node0 + cr1) * TT) * NIN + pcol);
    __syncthreads();

    for (int t = 1; t < TT; t++) {
        int pp = (t + 1) & 1, pn = t & 1;
        const __half* hp = g_h[pp];
        bool last = (t == TT - 1);

        // ---- own h (from resident hn) -> HH cols 128-255; prefetch W tile 0 -> WB(0) ----
        {
            int row = tid >> 4, seg = tid & 15;
            const float* hr = hn + row * 132 + seg * 8;
            __half hh[8];
            #pragma unroll
            for (int j = 0; j < 8; j++) hh[j] = __float2half_rn(hr[j]);
            *(uint4*)(sm + S_HH_HI + (row * 264 + 128 + seg * 8) * 2) = *(const uint4*)hh;
            // W tile 0 prefetch (WB buffers idle through all of phase A)
            #pragma unroll
            for (int i = 0; i < 4; i++) {
                int idx = i * 512 + tid;
                int wrow = idx >> 5, wseg = idx & 31;
                *(uint4*)(sm + WB(0) + (wrow * 264 + wseg * 8) * 2) =
                    *(const uint4*)(g_Wz + (long)wrow * NZ + wseg * 8);
            }
        }

        // ---- Phase A: H = An(resident) @ h (4 K-chunks of 128) ----
        float accA[2][4];
        #pragma unroll
        for (int nt = 0; nt < 2; nt++)
            #pragma unroll
            for (int q = 0; q < 4; q++) accA[nt][q] = 0.f;

        {
            #pragma unroll
            for (int i = 0; i < 4; i++) {
                int idx = i * 512 + tid;
                int hr = idx >> 4, hs = idx & 15;
                uint4 v = __ldcg((const uint4*)(hp + ((long)b * NN + hr) * NH) + hs);
                *(uint4*)(sm + S_HC + (hr * 136 + hs * 8) * 2) = v;
            }
        }
        __syncthreads();

        for (int c = 0; c < 4; c++) {
            uint4 sh[4];
            if (c < 3) {
                #pragma unroll
                for (int i = 0; i < 4; i++) {
                    int idx = i * 512 + tid;
                    int hr = idx >> 4, hs = idx & 15;
                    sh[i] = __ldcg((const uint4*)(hp + ((long)b * NN + (c + 1) * 128 + hr) * NH) + hs);
                }
            }
            #pragma unroll
            for (int kk = 0; kk < 8; kk++) {
                uint32_t aH[4], b0[4];
                uint32_t aoff = (uint32_t)(((wm * 16 + a_r) * 520 + c * 128 + kk * 16 + a_c) * 2);
                ldsm4(aH, smb + S_AN + aoff);
                uint32_t boff = (uint32_t)(((kk * 16 + bt_r) * 136 + wn * 16 + bt_c) * 2);
                ldsm4t(b0, smb + S_HC + boff);
                mma_f16(accA[0], aH, b0);
                mma_f16(accA[1], aH, b0 + 2);
            }
            __syncthreads();
            if (c < 3) {
                #pragma unroll
                for (int i = 0; i < 4; i++) {
                    int idx = i * 512 + tid;
                    int hr = idx >> 4, hs = idx & 15;
                    *(uint4*)(sm + S_HC + (hr * 136 + hs * 8) * 2) = sh[i];
                }
                __syncthreads();
            }
        }

        // ---- HH epilogue: H -> HH_HI cols 0-127 ----
        {
            int r0 = cr0, r1 = cr1;
            #pragma unroll
            for (int nt = 0; nt < 2; nt++) {
                int col = wn * 16 + nt * 8 + (lane & 3) * 2;
                __half2 ph;
                ph.x = __float2half_rn(accA[nt][0]);
                ph.y = __float2half_rn(accA[nt][1]);
                *(__half2*)(sm + S_HH_HI + (r0 * 264 + col) * 2) = ph;
                ph.x = __float2half_rn(accA[nt][2]);
                ph.y = __float2half_rn(accA[nt][3]);
                *(__half2*)(sm + S_HH_HI + (r1 * 264 + col) * 2) = ph;
            }
        }
        __syncthreads();

        // ---- Phase B: z = esW + [H|h] @ Wz (8 W tiles, dbl-buffered; tile0 prefetched) ----
        float accB[4][4];
        #pragma unroll
        for (int nt = 0; nt < 4; nt++)
            #pragma unroll
            for (int q = 0; q < 4; q++) accB[nt][q] = 0.f;

        for (int wt = 0; wt < 8; wt++) {
            int nc = wt >> 2, kc = wt & 3;
            uint4 stg[4];
            if (wt < 7) {
                int n2 = (wt + 1) >> 2, k2 = (wt + 1) & 3;
                #pragma unroll
                for (int i = 0; i < 4; i++) {
                    int idx = i * 512 + tid;
                    int row = idx >> 5, seg = idx & 31;
                    stg[i] = *(const uint4*)(g_Wz + (long)(k2 * 64 + row) * NZ + n2 * 256 + seg * 8);
                }
            }
            uint32_t wbuf = smb + WB(wt & 1);
            #pragma unroll
            for (int kk = 0; kk < 4; kk++) {
                uint32_t aH[4];
                uint32_t aoff = (uint32_t)(((wm * 16 + a_r) * 264 + kc * 64 + kk * 16 + a_c) * 2);
                ldsm4(aH, smb + S_HH_HI + aoff);
                uint32_t bf[2][4];
                #pragma unroll
                for (int p = 0; p < 2; p++) {
                    uint32_t boff = (uint32_t)(((kk * 16 + bt_r) * 264 + wn * 32 + p * 16 + bt_c) * 2);
                    ldsm4t(bf[p], wbuf + boff);
                }
                mma_f16(accB[0], aH, bf[0]);
                mma_f16(accB[1], aH, bf[0] + 2);
                mma_f16(accB[2], aH, bf[1]);
                mma_f16(accB[3], aH, bf[1] + 2);
            }
            if (wt < 7) {
                uint32_t wb2 = WB((wt + 1) & 1);
                #pragma unroll
                for (int i = 0; i < 4; i++) {
                    int idx = i * 512 + tid;
                    int row = idx >> 5, seg = idx & 31;
                    *(uint4*)(sm + wb2 + (row * 264 + seg * 8) * 2) = stg[i];
                }
            }
            __syncthreads();

            if (kc == 3) {
                float4 e4s[4];
                {
                    int row = tid >> 4, g16 = tid & 15;
                    long node = node0 + row;
                    #pragma unroll
                    for (int q = 0; q < 4; q++)
                        e4s[q] = *(const float4*)(g_esW + node * NZ + nc * 256 + q * 64 + g16 * 4);
                }
                {
                    int r0 = cr0, r1 = cr1;
                    #pragma unroll
                    for (int nt = 0; nt < 4; nt++) {
                        int col = wn * 32 + nt * 8 + (lane & 3) * 2;
                        zb[r0 * 260 + col]     = accB[nt][0];
                        zb[r0 * 260 + col + 1] = accB[nt][1];
                        zb[r1 * 260 + col]     = accB[nt][2];
                        zb[r1 * 260 + col + 1] = accB[nt][3];
                        #pragma unroll
                        for (int q = 0; q < 4; q++) accB[nt][q] = 0.f;
                    }
                }
                __syncthreads();
                {
                    int row = tid >> 4, g16 = tid & 15;
                    #pragma unroll
                    for (int q = 0; q < 4; q++) {
                        int ch = nc * 64 + q * 16 + g16;
                        int colz = q * 64 + g16 * 4;
                        float4 z4 = *(const float4*)(zb + row * 260 + colz);
                        float4 e4 = e4s[q];
                        float it = sigf(z4.x + e4.x);
                        float ft = sigf(z4.y + e4.y);
                        float gt = tanhf(z4.z + e4.z);
                        float ot = sigf(z4.w + e4.w);
                        float cn = ft * sc[row * 132 + ch] + it * gt;
                        float hv = ot * tanhf(cn);
                        sc[row * 132 + ch] = cn;
                        hn[row * 132 + ch] = hv;
                    }
                }
                __syncthreads();
            }
        }

        // ---- writeback h(fp16, L2); stage hn split + Wo tiles ----
        {
            __half* hw = g_h[pn];
            #pragma unroll
            for (int i = 0; i < 2; i++) {
                int idx = i * 512 + tid;
                int row = idx >> 5, c4 = (idx & 31) * 4;
                long base = (node0 + row) * NH + c4;
                float4 hv4 = *(const float4*)(hn + row * 132 + c4);
                __half hh[4];
                hh[0] = __float2half_rn(hv4.x); hh[1] = __float2half_rn(hv4.y);
                hh[2] = __float2half_rn(hv4.z); hh[3] = __float2half_rn(hv4.w);
                __stcg((uint2*)(hw + base), *(const uint2*)hh);
            }
            #pragma unroll
            for (int i = 0; i < 4; i++) {
                int idx = i * 512 + tid;
                int row = idx >> 6, c2 = (idx & 63) * 2;
                float hv0 = hn[row * 132 + c2], hv1 = hn[row * 132 + c2 + 1];
                __half h0, l0, h1, l1;
                split_h(hv0, h0, l0); split_h(hv1, h1, l1);
                __half2 ph; ph.x = h0; ph.y = h1;
                __half2 pl; pl.x = l0; pl.y = l1;
                *(__half2*)(sm + S_HH_HI + (row * 264 + c2) * 2) = ph;
                *(__half2*)(sm + S_HH_LO + (row * 264 + c2) * 2) = pl;
            }
            #pragma unroll
            for (int i = 0; i < 2; i++) {
                int idx = i * 512 + tid;
                int row = idx >> 3, seg = idx & 7;
                *(uint4*)(sm + WB(0) + (row * 72 + seg * 8) * 2) =
                    *((const uint4*)(g_Wo_hi + row * NIN) + seg);
                *(uint4*)(sm + WB(1) + (row * 72 + seg * 8) * 2) =
                    *((const uint4*)(g_Wo_lo + row * NIN) + seg);
            }
        }
        __threadfence();
        __syncthreads();

        // ---- EARLY per-batch arrive (h published); wait deferred past phase C ----
        if (!last && tid == 0) {
            int v = atomicAdd(&g_barc[b], 1);
            if (v == 16 * t - 1) atomicExch(&g_barg[b], t);
        }

        // ---- Phase C: out[t] = out[t-1](regs) + hn @ Wout + bout ----
        {
            float accC[4] = {0.f, 0.f, 0.f, 0.f};
            #pragma unroll
            for (int kk = 0; kk < 8; kk++) {
                uint32_t aH[4], aL[4], bH[2], bL[2];
                uint32_t aoff = (uint32_t)(((wm * 16 + a_r) * 264 + kk * 16 + a_c) * 2);
                ldsm4(aH, smb + S_HH_HI + aoff);
                ldsm4(aL, smb + S_HH_LO + aoff);
                uint32_t boff = (uint32_t)(((kk * 16 + bt_r) * 72 + wn * 8) * 2);
                ldsm2t(bH, smb + WB(0) + boff);
                ldsm2t(bL, smb + WB(1) + boff);
                mma_f16(accC, aH, bH);
                mma_f16(accC, aH, bL);
                mma_f16(accC, aL, bH);
            }
            orun0.x = (orun0.x + accC[0]) + b0v;
            orun0.y = (orun0.y + accC[1]) + b1v;
            orun1.x = (orun1.x + accC[2]) + b0v;
            orun1.y = (orun1.y + accC[3]) + b1v;
            long ob0 = (((node0 + cr0) * TT) + t) * NIN + pcol;
            long ob1 = (((node0 + cr1) * TT) + t) * NIN + pcol;
            *(float2*)(out + ob0) = orun0;
            *(float2*)(out + ob1) = orun1;
        }

        // ---- per-batch barrier wait (overlapped with phase C above) ----
        if (!last) {
            if (tid == 0) {
                while (*((volatile int*)&g_barg[b]) < t) { }
            }
            __syncthreads();
        }
    }
}

// ---------------- launch ----------------
extern "C" void kernel_launch(void* const* d_in, const int* in_sizes, int n_in,
                              void* d_out, int out_size) {
    (void)in_sizes; (void)n_in; (void)out_size;
    const float* X    = (const float*)d_in[0];
    const float* A    = (const float*)d_in[1];
    const float* Wse  = (const float*)d_in[2];
    const float* bse  = (const float*)d_in[3];
    const float* Wpe  = (const float*)d_in[4];
    const float* bpe  = (const float*)d_in[5];
    const float* Wii  = (const float*)d_in[6];
    const float* bii  = (const float*)d_in[7];
    const float* Whi  = (const float*)d_in[8];
    const float* bhi  = (const float*)d_in[9];
    const float* Wif  = (const float*)d_in[10];
    const float* bif  = (const float*)d_in[11];
    const float* Whf  = (const float*)d_in[12];
    const float* bhf  = (const float*)d_in[13];
    const float* Wig  = (const float*)d_in[14];
    const float* big  = (const float*)d_in[15];
    const float* Whg  = (const float*)d_in[16];
    const float* bhg  = (const float*)d_in[17];
    const float* Wio  = (const float*)d_in[18];
    const float* bio  = (const float*)d_in[19];
    const float* Who  = (const float*)d_in[20];
    const float* bho  = (const float*)d_in[21];
    const float* Wout = (const float*)d_in[22];
    const float* bout = (const float*)d_in[23];
    float* out = (float*)d_out;

    cudaFuncSetAttribute(k_steps, cudaFuncAttributeMaxDynamicSharedMemorySize, SMEM_TOT);

    k_dinv<<<BB * NN, 128>>>(A);
    k_an<<<(BB * NN * NN) / 256, 256>>>(A);
    k_es<<<(NODES * NE) / 256, 256>>>(X, Wse, bse, out);
    k_wz<<<(256 * NZ) / 256, 256>>>(Wpe, bpe, Wii, bii, Whi, bhi, Wif, bif,
                                    Whf, bhf, Wig, big, Whg, bhg,
                                    Wio, bio, Who, bho);
    k_esw<<<(NODES * NZ) / 256, 256>>>(Wii, Wif, Wig, Wio);
    k_wo<<<(NH * NIN) / 256, 256>>>(Wout);
    k_zero<<<(NODES * NH) / 256, 256>>>();

    k_steps<<<128, 512, SMEM_TOT>>>(bout, out);
}